// round 6
// baseline (speedup 1.0000x reference)
#include <cuda_runtime.h>
#include <cstdint>
#include <math.h>

#define B_   8
#define C_   512
#define N_   2048
#define GROUPS_ 32
#define CPG  16
#define EPSF 1e-6f

#define NC_ ((size_t)N_ * C_)      // 1048576
#define NN_ ((size_t)N_ * N_)      // 4194304

// ---------------- scratch ----------------
__device__ float g_hT [B_ * N_ * C_];          // groupnorm out, [b][n][c]
__device__ float g_qT [B_ * N_ * C_];          // [b][n][c]
__device__ float g_kT [B_ * N_ * C_];          // [b][n][c]
__device__ float g_v  [B_ * C_ * N_];          // [b][c][n]
__device__ float g_p  [(size_t)B_ * N_ * N_];  // [b][i][j]
__device__ float g_h2T[B_ * N_ * C_];          // [b][i][c]

// ---------------- helpers ----------------
__device__ __forceinline__ uint32_t smem_u32(const void* p) {
    uint32_t a;
    asm("{ .reg .u64 t; cvta.to.shared.u64 t, %1; cvt.u32.u64 %0, t; }" : "=r"(a) : "l"(p));
    return a;
}
__device__ __forceinline__ void cp_async16(uint32_t dst, const void* src) {
    asm volatile("cp.async.cg.shared.global [%0], [%1], 16;" :: "r"(dst), "l"(src));
}
#define CP_COMMIT() asm volatile("cp.async.commit_group;" ::: "memory")
#define CP_WAIT1()  asm volatile("cp.async.wait_group 1;" ::: "memory")

// mma.tf32 accepts raw fp32 bit patterns; tensor core truncates mantissa (CUTLASS-style,
// no per-element cvt in the mainloop).
__device__ __forceinline__ void mma_tf32(float* c, const uint32_t* a, const uint32_t* b) {
    asm volatile("mma.sync.aligned.m16n8k8.row.col.f32.tf32.tf32.f32 "
                 "{%0,%1,%2,%3}, {%4,%5,%6,%7}, {%8,%9}, {%0,%1,%2,%3};"
                 : "+f"(c[0]), "+f"(c[1]), "+f"(c[2]), "+f"(c[3])
                 : "r"(a[0]), "r"(a[1]), "r"(a[2]), "r"(a[3]), "r"(b[0]), "r"(b[1]));
}

// ---------------- GroupNorm (writes transposed hT[b][n][c] via smem tile) ----------------
__global__ __launch_bounds__(256) void groupnorm_kernel(const float* __restrict__ x,
                                                        const float* __restrict__ scale,
                                                        const float* __restrict__ bias) {
    int bg = blockIdx.x;
    int b = bg / GROUPS_, g = bg % GROUPS_;
    const float* xp  = x + ((size_t)b * C_ + (size_t)g * CPG) * N_;
    float*       hpT = g_hT + (size_t)b * NC_;
    int tid = threadIdx.x;
    const int total = CPG * N_;  // 32768

    float s = 0.f, ss = 0.f;
    for (int i = tid; i < total; i += 256) {
        float v = xp[i];
        s += v; ss += v * v;
    }
    __shared__ float rs[256], rq[256];
    rs[tid] = s; rq[tid] = ss;
    __syncthreads();
    for (int off = 128; off > 0; off >>= 1) {
        if (tid < off) { rs[tid] += rs[tid + off]; rq[tid] += rq[tid + off]; }
        __syncthreads();
    }
    float mean = rs[0] / (float)total;
    float var  = rq[0] / (float)total - mean * mean;
    float rinv = rsqrtf(var + EPSF);

    __shared__ float tile[128][17];
    for (int n0 = 0; n0 < N_; n0 += 128) {
        __syncthreads();
        int nl = tid & 127;
        int ch = tid >> 7;               // 0 or 1
        #pragma unroll
        for (int cp = 0; cp < 8; cp++) {
            int c = cp * 2 + ch;         // 0..15
            int cabs = g * CPG + c;
            tile[nl][c] = (xp[(size_t)c * N_ + n0 + nl] - mean) * rinv * scale[cabs] + bias[cabs];
        }
        __syncthreads();
        int row = tid >> 1;              // 0..127
        int half = (tid & 1) * 8;        // 0 or 8
        float* dst = hpT + (size_t)(n0 + row) * C_ + g * CPG + half;
        float4 o0, o1;
        o0.x = tile[row][half + 0]; o0.y = tile[row][half + 1];
        o0.z = tile[row][half + 2]; o0.w = tile[row][half + 3];
        o1.x = tile[row][half + 4]; o1.y = tile[row][half + 5];
        o1.z = tile[row][half + 6]; o1.w = tile[row][half + 7];
        *(float4*)(dst + 0) = o0;
        *(float4*)(dst + 4) = o1;
    }
}

// ---------------- tf32 mma.sync GEMM ----------------
// D[m][n] = sum_k A[m][k] * B[n][k], both K-major. Tile 128x128x16, cp.async 2-stage.
#define MODE_COLB  0
#define MODE_ROWB  1
#define MODE_SCALE 2
#define MODE_NONE  3
#define MODE_OUT   4

#define BK   16
#define PAD  20   // row pitch in floats; (20m+k)%32 distinct over 8m x 4k footprint

template <int MODE>
__global__ __launch_bounds__(256, 2)
void gemm_kernel(const float* __restrict__ A, const float* __restrict__ Bm,
                 float* __restrict__ D,
                 const float* __restrict__ bias, const float* __restrict__ resid,
                 int lda, int ldb, int ldd, int K,
                 size_t a_bs, size_t b_bs, size_t d_bs, size_t r_bs) {
    __shared__ float sA[2][128 * PAD];   // 10 KB each
    __shared__ float sB[2][128 * PAD];

    int tid = threadIdx.x, lane = tid & 31, wid = tid >> 5;
    int warp_m = wid & 3;                // 4 warps over M
    int warp_n = wid >> 2;               // 2 warps over N

    int b  = blockIdx.z;
    int m0 = blockIdx.y * 128, n0 = blockIdx.x * 128;
    const float* Ab = A  + (size_t)b * a_bs;
    const float* Bb = Bm + (size_t)b * b_bs;
    float*       Db = D  + (size_t)b * d_bs;

    uint32_t saddr = smem_u32(sA);
    uint32_t baddr = smem_u32(sB);

    // global-load mapping: 512 float4 per operand per chunk
    int lr0 = tid >> 2, lc0 = tid & 3;          // row 0..63, col 0..3
    int lr1 = lr0 + 64;

    auto load_stage = [&](int stage, int k0) {
        uint32_t sa = saddr + (uint32_t)stage * 128 * PAD * 4;
        uint32_t sb = baddr + (uint32_t)stage * 128 * PAD * 4;
        cp_async16(sa + (uint32_t)(lr0 * PAD + lc0 * 4) * 4, Ab + (size_t)(m0 + lr0) * lda + k0 + lc0 * 4);
        cp_async16(sa + (uint32_t)(lr1 * PAD + lc0 * 4) * 4, Ab + (size_t)(m0 + lr1) * lda + k0 + lc0 * 4);
        cp_async16(sb + (uint32_t)(lr0 * PAD + lc0 * 4) * 4, Bb + (size_t)(n0 + lr0) * ldb + k0 + lc0 * 4);
        cp_async16(sb + (uint32_t)(lr1 * PAD + lc0 * 4) * 4, Bb + (size_t)(n0 + lr1) * ldb + k0 + lc0 * 4);
    };

    float acc[2][8][4];
    #pragma unroll
    for (int i = 0; i < 2; i++)
        #pragma unroll
        for (int j = 0; j < 8; j++)
            #pragma unroll
            for (int t = 0; t < 4; t++) acc[i][j][t] = 0.f;

    const int nck = K / BK;
    load_stage(0, 0);
    CP_COMMIT();

    for (int ck = 0; ck < nck; ck++) {
        if (ck + 1 < nck) load_stage((ck + 1) & 1, (ck + 1) * BK);
        CP_COMMIT();
        CP_WAIT1();
        __syncthreads();

        const float* sa = sA[ck & 1];
        const float* sb = sB[ck & 1];
        int arow = warp_m * 32 + (lane >> 2);
        int brow = warp_n * 64 + (lane >> 2);
        int kq   = lane & 3;

        #pragma unroll
        for (int kk = 0; kk < 2; kk++) {
            int kbase = kk * 8 + kq;
            uint32_t af[2][4];
            #pragma unroll
            for (int mt = 0; mt < 2; mt++) {
                const float* ap = sa + (arow + mt * 16) * PAD + kbase;
                af[mt][0] = __float_as_uint(ap[0]);
                af[mt][1] = __float_as_uint(ap[8 * PAD]);
                af[mt][2] = __float_as_uint(ap[4]);
                af[mt][3] = __float_as_uint(ap[8 * PAD + 4]);
            }
            uint32_t bf[8][2];
            #pragma unroll
            for (int nt = 0; nt < 8; nt++) {
                const float* bp = sb + (brow + nt * 8) * PAD + kbase;
                bf[nt][0] = __float_as_uint(bp[0]);
                bf[nt][1] = __float_as_uint(bp[4]);
            }
            #pragma unroll
            for (int mt = 0; mt < 2; mt++)
                #pragma unroll
                for (int nt = 0; nt < 8; nt++)
                    mma_tf32(acc[mt][nt], af[mt], bf[nt]);
        }
        __syncthreads();
    }

    // epilogue: c0,c1 -> (row, col), (row, col+1); c2,c3 -> (row+8, col..)
    int rbase = m0 + warp_m * 32 + (lane >> 2);
    int cbase = n0 + warp_n * 64 + (lane & 3) * 2;
    #pragma unroll
    for (int mt = 0; mt < 2; mt++) {
        int r0 = rbase + mt * 16;
        int r1 = r0 + 8;
        float rb0 = 0.f, rb1 = 0.f;
        if (MODE == MODE_ROWB || MODE == MODE_OUT) { rb0 = bias[r0]; rb1 = bias[r1]; }
        #pragma unroll
        for (int nt = 0; nt < 8; nt++) {
            int cc = cbase + nt * 8;
            float e0 = acc[mt][nt][0], e1 = acc[mt][nt][1];
            float e2 = acc[mt][nt][2], e3 = acc[mt][nt][3];
            if (MODE == MODE_COLB) {
                float b0 = bias[cc], b1 = bias[cc + 1];
                e0 += b0; e1 += b1; e2 += b0; e3 += b1;
            } else if (MODE == MODE_SCALE) {
                const float scl = 0.044194173824159216f;
                e0 *= scl; e1 *= scl; e2 *= scl; e3 *= scl;
            } else if (MODE == MODE_ROWB) {
                e0 += rb0; e1 += rb0; e2 += rb1; e3 += rb1;
            } else if (MODE == MODE_OUT) {
                const float* rp0 = resid + (size_t)b * r_bs + (size_t)r0 * ldd + cc;
                const float* rp1 = resid + (size_t)b * r_bs + (size_t)r1 * ldd + cc;
                e0 += rb0 + rp0[0]; e1 += rb0 + rp0[1];
                e2 += rb1 + rp1[0]; e3 += rb1 + rp1[1];
            }
            float2 o0; o0.x = e0; o0.y = e1;
            float2 o1; o1.x = e2; o1.y = e3;
            *(float2*)(Db + (size_t)r0 * ldd + cc) = o0;
            *(float2*)(Db + (size_t)r1 * ldd + cc) = o1;
        }
    }
}

// ---------------- row softmax ----------------
__global__ __launch_bounds__(256) void softmax_kernel() {
    size_t row = blockIdx.x;
    float* p = g_p + row * N_;
    int tid = threadIdx.x;

    float v[8];
    float mx = -1e30f;
    #pragma unroll
    for (int j = 0; j < 8; j++) { v[j] = p[tid + j * 256]; mx = fmaxf(mx, v[j]); }

    __shared__ float red[256];
    red[tid] = mx; __syncthreads();
    for (int off = 128; off > 0; off >>= 1) {
        if (tid < off) red[tid] = fmaxf(red[tid], red[tid + off]);
        __syncthreads();
    }
    mx = red[0]; __syncthreads();

    float s = 0.f;
    #pragma unroll
    for (int j = 0; j < 8; j++) { v[j] = expf(v[j] - mx); s += v[j]; }
    red[tid] = s; __syncthreads();
    for (int off = 128; off > 0; off >>= 1) {
        if (tid < off) red[tid] += red[tid + off];
        __syncthreads();
    }
    float rinv = 1.f / red[0];
    #pragma unroll
    for (int j = 0; j < 8; j++) p[tid + j * 256] = v[j] * rinv;
}

// ---------------- launch ----------------
extern "C" void kernel_launch(void* const* d_in, const int* in_sizes, int n_in,
                              void* d_out, int out_size) {
    const float* x  = (const float*)d_in[0];
    const float* gs = (const float*)d_in[1];
    const float* gb = (const float*)d_in[2];
    const float* wq = (const float*)d_in[3];
    const float* bq = (const float*)d_in[4];
    const float* wk = (const float*)d_in[5];
    const float* bk = (const float*)d_in[6];
    const float* wv = (const float*)d_in[7];
    const float* bv = (const float*)d_in[8];
    const float* wp = (const float*)d_in[9];
    const float* bp = (const float*)d_in[10];
    float* out = (float*)d_out;

    float* hT  = nullptr; cudaGetSymbolAddress((void**)&hT,  g_hT);
    float* qT  = nullptr; cudaGetSymbolAddress((void**)&qT,  g_qT);
    float* kT  = nullptr; cudaGetSymbolAddress((void**)&kT,  g_kT);
    float* v   = nullptr; cudaGetSymbolAddress((void**)&v,   g_v);
    float* p   = nullptr; cudaGetSymbolAddress((void**)&p,   g_p);
    float* h2T = nullptr; cudaGetSymbolAddress((void**)&h2T, g_h2T);

    groupnorm_kernel<<<B_ * GROUPS_, 256>>>(x, gs, gb);

    // qT[n][o] = sum_c hT[n][c] wq[o][c] + bq[o]      M=2048 N=512 K=512
    gemm_kernel<MODE_COLB><<<dim3(4, 16, B_), 256>>>(
        hT, wq, qT, bq, nullptr, C_, C_, C_, C_, NC_, 0, NC_, 0);
    // kT
    gemm_kernel<MODE_COLB><<<dim3(4, 16, B_), 256>>>(
        hT, wk, kT, bk, nullptr, C_, C_, C_, C_, NC_, 0, NC_, 0);
    // v[o][n] = sum_c wv[o][c] hT[n][c] + bv[o]       M=512 N=2048 K=512
    gemm_kernel<MODE_ROWB><<<dim3(16, 4, B_), 256>>>(
        wv, hT, v, bv, nullptr, C_, C_, N_, C_, 0, NC_, NC_, 0);
    // P[i][j] = scale * sum_c qT[i][c] kT[j][c]       M=2048 N=2048 K=512
    gemm_kernel<MODE_SCALE><<<dim3(16, 16, B_), 256>>>(
        qT, kT, p, nullptr, nullptr, C_, C_, N_, C_, NC_, NC_, NN_, 0);

    softmax_kernel<<<B_ * N_, 256>>>();

    // h2T[i][c] = sum_j P[i][j] v[c][j]               M=2048 N=512 K=2048
    gemm_kernel<MODE_NONE><<<dim3(4, 16, B_), 256>>>(
        p, v, h2T, nullptr, nullptr, N_, N_, C_, N_, NN_, NC_, NC_, 0);
    // out[o][n] = x + bp[o] + sum_c wp[o][c] h2T[n][c]  M=512 N=2048 K=512
    gemm_kernel<MODE_OUT><<<dim3(16, 4, B_), 256>>>(
        wp, h2T, out, bp, x, C_, C_, N_, C_, 0, NC_, NC_, NC_);
}

// round 7
// speedup vs baseline: 1.1312x; 1.1312x over previous
#include <cuda_runtime.h>
#include <cstdint>
#include <math.h>

#define B_   8
#define C_   512
#define N_   2048
#define GROUPS_ 32
#define CPG  16
#define EPSF 1e-6f

#define NC_ ((size_t)N_ * C_)      // 1048576
#define NN_ ((size_t)N_ * N_)      // 4194304

// ---------------- scratch ----------------
__device__ float g_hT [B_ * N_ * C_];          // groupnorm out, [b][n][c]
__device__ float g_qT [B_ * N_ * C_];          // [b][n][c]
__device__ float g_kT [B_ * N_ * C_];          // [b][n][c]
__device__ float g_v  [B_ * C_ * N_];          // [b][c][n]
__device__ float g_p  [(size_t)B_ * N_ * N_];  // [b][i][j]
__device__ float g_h2T[B_ * N_ * C_];          // [b][i][c]

// ---------------- helpers ----------------
__device__ __forceinline__ uint32_t smem_u32(const void* p) {
    uint32_t a;
    asm("{ .reg .u64 t; cvta.to.shared.u64 t, %1; cvt.u32.u64 %0, t; }" : "=r"(a) : "l"(p));
    return a;
}
__device__ __forceinline__ void cp_async16(uint32_t dst, const void* src) {
    asm volatile("cp.async.cg.shared.global [%0], [%1], 16;" :: "r"(dst), "l"(src));
}
#define CP_COMMIT() asm volatile("cp.async.commit_group;" ::: "memory")
#define CP_WAIT1()  asm volatile("cp.async.wait_group 1;" ::: "memory")

// mma.tf32 accepts raw fp32 bit patterns; tensor core truncates the mantissa.
__device__ __forceinline__ void mma_tf32(float* c, const uint32_t* a, const uint32_t* b) {
    asm volatile("mma.sync.aligned.m16n8k8.row.col.f32.tf32.tf32.f32 "
                 "{%0,%1,%2,%3}, {%4,%5,%6,%7}, {%8,%9}, {%0,%1,%2,%3};"
                 : "+f"(c[0]), "+f"(c[1]), "+f"(c[2]), "+f"(c[3])
                 : "r"(a[0]), "r"(a[1]), "r"(a[2]), "r"(a[3]), "r"(b[0]), "r"(b[1]));
}

// ---------------- GroupNorm (writes transposed hT[b][n][c] via smem tile) ----------------
__global__ __launch_bounds__(256) void groupnorm_kernel(const float* __restrict__ x,
                                                        const float* __restrict__ scale,
                                                        const float* __restrict__ bias) {
    int bg = blockIdx.x;
    int b = bg / GROUPS_, g = bg % GROUPS_;
    const float* xp  = x + ((size_t)b * C_ + (size_t)g * CPG) * N_;
    float*       hpT = g_hT + (size_t)b * NC_;
    int tid = threadIdx.x;
    const int total = CPG * N_;  // 32768

    float s = 0.f, ss = 0.f;
    for (int i = tid; i < total; i += 256) {
        float v = xp[i];
        s += v; ss += v * v;
    }
    __shared__ float rs[256], rq[256];
    rs[tid] = s; rq[tid] = ss;
    __syncthreads();
    for (int off = 128; off > 0; off >>= 1) {
        if (tid < off) { rs[tid] += rs[tid + off]; rq[tid] += rq[tid + off]; }
        __syncthreads();
    }
    float mean = rs[0] / (float)total;
    float var  = rq[0] / (float)total - mean * mean;
    float rinv = rsqrtf(var + EPSF);

    __shared__ float tile[128][17];
    for (int n0 = 0; n0 < N_; n0 += 128) {
        __syncthreads();
        int nl = tid & 127;
        int ch = tid >> 7;               // 0 or 1
        #pragma unroll
        for (int cp = 0; cp < 8; cp++) {
            int c = cp * 2 + ch;         // 0..15
            int cabs = g * CPG + c;
            tile[nl][c] = (xp[(size_t)c * N_ + n0 + nl] - mean) * rinv * scale[cabs] + bias[cabs];
        }
        __syncthreads();
        int row = tid >> 1;              // 0..127
        int half = (tid & 1) * 8;        // 0 or 8
        float* dst = hpT + (size_t)(n0 + row) * C_ + g * CPG + half;
        float4 o0, o1;
        o0.x = tile[row][half + 0]; o0.y = tile[row][half + 1];
        o0.z = tile[row][half + 2]; o0.w = tile[row][half + 3];
        o1.x = tile[row][half + 4]; o1.y = tile[row][half + 5];
        o1.z = tile[row][half + 6]; o1.w = tile[row][half + 7];
        *(float4*)(dst + 0) = o0;
        *(float4*)(dst + 4) = o1;
    }
}

// ---------------- tf32 mma.sync GEMM ----------------
// D[m][n] = sum_k A[m][k] * B[n][k], both K-major.
// Tile 128x128x32, 3-stage cp.async circular buffer, one __syncthreads per chunk.
#define MODE_COLB  0
#define MODE_ROWB  1
#define MODE_SCALE 2
#define MODE_NONE  3
#define MODE_OUT   4

#define BK    32
#define PAD   36           // pitch in floats; 36 % 32 = 4 -> banks (4m+k)%32 distinct over 8m x 4k
#define STAGEF (128 * PAD) // floats per operand per stage
#define GSMEM  (3 * 2 * STAGEF * 4)   // 110592 bytes

template <int MODE>
__global__ __launch_bounds__(256, 2)
void gemm_kernel(const float* __restrict__ A, const float* __restrict__ Bm,
                 float* __restrict__ D,
                 const float* __restrict__ bias, const float* __restrict__ resid,
                 int lda, int ldb, int ldd, int K,
                 size_t a_bs, size_t b_bs, size_t d_bs, size_t r_bs) {
    extern __shared__ float smem[];   // [stage][A|B][STAGEF]

    int tid = threadIdx.x, lane = tid & 31, wid = tid >> 5;
    int warp_m = wid & 3;                // 4 warps over M
    int warp_n = wid >> 2;               // 2 warps over N

    int b  = blockIdx.z;
    int m0 = blockIdx.y * 128, n0 = blockIdx.x * 128;
    const float* Ab = A  + (size_t)b * a_bs;
    const float* Bb = Bm + (size_t)b * b_bs;
    float*       Db = D  + (size_t)b * d_bs;

    uint32_t sbase = smem_u32(smem);

    // global->smem: 1024 float4 per operand per stage; 4 per thread per operand
    auto load_stage = [&](int stage, int k0) {
        uint32_t sa = sbase + (uint32_t)stage * (2u * STAGEF * 4u);
        uint32_t sb = sa + STAGEF * 4u;
        #pragma unroll
        for (int t = 0; t < 4; t++) {
            int idx = t * 256 + tid;
            int r = idx >> 3, c = idx & 7;
            uint32_t off = (uint32_t)(r * PAD + c * 4) * 4u;
            cp_async16(sa + off, Ab + (size_t)(m0 + r) * lda + k0 + c * 4);
            cp_async16(sb + off, Bb + (size_t)(n0 + r) * ldb + k0 + c * 4);
        }
    };

    float acc[2][8][4];
    #pragma unroll
    for (int i = 0; i < 2; i++)
        #pragma unroll
        for (int j = 0; j < 8; j++)
            #pragma unroll
            for (int t = 0; t < 4; t++) acc[i][j][t] = 0.f;

    const int nck = K / BK;
    load_stage(0, 0);
    CP_COMMIT();
    load_stage(1, BK);
    CP_COMMIT();

    int stage = 0;               // ck % 3
    for (int ck = 0; ck < nck; ck++) {
        CP_WAIT1();              // stage ck resident (ck+1 may still be in flight)
        __syncthreads();         // also: all warps done with buffer (ck-1)%3 == (ck+2)%3

        int nstage = stage + 2; if (nstage >= 3) nstage -= 3;
        if (ck + 2 < nck) load_stage(nstage, (ck + 2) * BK);
        CP_COMMIT();             // unconditional: keeps wait_group arithmetic uniform

        const float* sa = smem + (size_t)stage * 2 * STAGEF;
        const float* sb = sa + STAGEF;
        int arow = warp_m * 32 + (lane >> 2);
        int brow = warp_n * 64 + (lane >> 2);
        int kq   = lane & 3;

        #pragma unroll
        for (int kk = 0; kk < 4; kk++) {
            int kbase = kk * 8 + kq;
            uint32_t af[2][4];
            #pragma unroll
            for (int mt = 0; mt < 2; mt++) {
                const float* ap = sa + (arow + mt * 16) * PAD + kbase;
                af[mt][0] = __float_as_uint(ap[0]);
                af[mt][1] = __float_as_uint(ap[8 * PAD]);
                af[mt][2] = __float_as_uint(ap[4]);
                af[mt][3] = __float_as_uint(ap[8 * PAD + 4]);
            }
            uint32_t bf[8][2];
            #pragma unroll
            for (int nt = 0; nt < 8; nt++) {
                const float* bp = sb + (brow + nt * 8) * PAD + kbase;
                bf[nt][0] = __float_as_uint(bp[0]);
                bf[nt][1] = __float_as_uint(bp[4]);
            }
            #pragma unroll
            for (int mt = 0; mt < 2; mt++)
                #pragma unroll
                for (int nt = 0; nt < 8; nt++)
                    mma_tf32(acc[mt][nt], af[mt], bf[nt]);
        }

        if (++stage == 3) stage = 0;
    }

    // epilogue
    int rbase = m0 + warp_m * 32 + (lane >> 2);
    int cbase = n0 + warp_n * 64 + (lane & 3) * 2;
    #pragma unroll
    for (int mt = 0; mt < 2; mt++) {
        int r0 = rbase + mt * 16;
        int r1 = r0 + 8;
        float rb0 = 0.f, rb1 = 0.f;
        if (MODE == MODE_ROWB || MODE == MODE_OUT) { rb0 = bias[r0]; rb1 = bias[r1]; }
        #pragma unroll
        for (int nt = 0; nt < 8; nt++) {
            int cc = cbase + nt * 8;
            float e0 = acc[mt][nt][0], e1 = acc[mt][nt][1];
            float e2 = acc[mt][nt][2], e3 = acc[mt][nt][3];
            if (MODE == MODE_COLB) {
                float b0 = bias[cc], b1 = bias[cc + 1];
                e0 += b0; e1 += b1; e2 += b0; e3 += b1;
            } else if (MODE == MODE_SCALE) {
                const float scl = 0.044194173824159216f;
                e0 *= scl; e1 *= scl; e2 *= scl; e3 *= scl;
            } else if (MODE == MODE_ROWB) {
                e0 += rb0; e1 += rb0; e2 += rb1; e3 += rb1;
            } else if (MODE == MODE_OUT) {
                const float* rp0 = resid + (size_t)b * r_bs + (size_t)r0 * ldd + cc;
                const float* rp1 = resid + (size_t)b * r_bs + (size_t)r1 * ldd + cc;
                e0 += rb0 + rp0[0]; e1 += rb0 + rp0[1];
                e2 += rb1 + rp1[0]; e3 += rb1 + rp1[1];
            }
            float2 o0; o0.x = e0; o0.y = e1;
            float2 o1; o1.x = e2; o1.y = e3;
            *(float2*)(Db + (size_t)r0 * ldd + cc) = o0;
            *(float2*)(Db + (size_t)r1 * ldd + cc) = o1;
        }
    }
}

// ---------------- row softmax ----------------
__global__ __launch_bounds__(256) void softmax_kernel() {
    size_t row = blockIdx.x;
    float* p = g_p + row * N_;
    int tid = threadIdx.x;

    float v[8];
    float mx = -1e30f;
    #pragma unroll
    for (int j = 0; j < 8; j++) { v[j] = p[tid + j * 256]; mx = fmaxf(mx, v[j]); }

    __shared__ float red[256];
    red[tid] = mx; __syncthreads();
    for (int off = 128; off > 0; off >>= 1) {
        if (tid < off) red[tid] = fmaxf(red[tid], red[tid + off]);
        __syncthreads();
    }
    mx = red[0]; __syncthreads();

    float s = 0.f;
    #pragma unroll
    for (int j = 0; j < 8; j++) { v[j] = expf(v[j] - mx); s += v[j]; }
    red[tid] = s; __syncthreads();
    for (int off = 128; off > 0; off >>= 1) {
        if (tid < off) red[tid] += red[tid + off];
        __syncthreads();
    }
    float rinv = 1.f / red[0];
    #pragma unroll
    for (int j = 0; j < 8; j++) p[tid + j * 256] = v[j] * rinv;
}

// ---------------- launch ----------------
extern "C" void kernel_launch(void* const* d_in, const int* in_sizes, int n_in,
                              void* d_out, int out_size) {
    const float* x  = (const float*)d_in[0];
    const float* gs = (const float*)d_in[1];
    const float* gb = (const float*)d_in[2];
    const float* wq = (const float*)d_in[3];
    const float* bq = (const float*)d_in[4];
    const float* wk = (const float*)d_in[5];
    const float* bk = (const float*)d_in[6];
    const float* wv = (const float*)d_in[7];
    const float* bv = (const float*)d_in[8];
    const float* wp = (const float*)d_in[9];
    const float* bp = (const float*)d_in[10];
    float* out = (float*)d_out;

    cudaFuncSetAttribute(gemm_kernel<MODE_COLB>,  cudaFuncAttributeMaxDynamicSharedMemorySize, GSMEM);
    cudaFuncSetAttribute(gemm_kernel<MODE_ROWB>,  cudaFuncAttributeMaxDynamicSharedMemorySize, GSMEM);
    cudaFuncSetAttribute(gemm_kernel<MODE_SCALE>, cudaFuncAttributeMaxDynamicSharedMemorySize, GSMEM);
    cudaFuncSetAttribute(gemm_kernel<MODE_NONE>,  cudaFuncAttributeMaxDynamicSharedMemorySize, GSMEM);
    cudaFuncSetAttribute(gemm_kernel<MODE_OUT>,   cudaFuncAttributeMaxDynamicSharedMemorySize, GSMEM);

    float* hT  = nullptr; cudaGetSymbolAddress((void**)&hT,  g_hT);
    float* qT  = nullptr; cudaGetSymbolAddress((void**)&qT,  g_qT);
    float* kT  = nullptr; cudaGetSymbolAddress((void**)&kT,  g_kT);
    float* v   = nullptr; cudaGetSymbolAddress((void**)&v,   g_v);
    float* p   = nullptr; cudaGetSymbolAddress((void**)&p,   g_p);
    float* h2T = nullptr; cudaGetSymbolAddress((void**)&h2T, g_h2T);

    groupnorm_kernel<<<B_ * GROUPS_, 256>>>(x, gs, gb);

    // qT[n][o] = sum_c hT[n][c] wq[o][c] + bq[o]      M=2048 N=512 K=512
    gemm_kernel<MODE_COLB><<<dim3(4, 16, B_), 256, GSMEM>>>(
        hT, wq, qT, bq, nullptr, C_, C_, C_, C_, NC_, 0, NC_, 0);
    // kT
    gemm_kernel<MODE_COLB><<<dim3(4, 16, B_), 256, GSMEM>>>(
        hT, wk, kT, bk, nullptr, C_, C_, C_, C_, NC_, 0, NC_, 0);
    // v[o][n] = sum_c wv[o][c] hT[n][c] + bv[o]       M=512 N=2048 K=512
    gemm_kernel<MODE_ROWB><<<dim3(16, 4, B_), 256, GSMEM>>>(
        wv, hT, v, bv, nullptr, C_, C_, N_, C_, 0, NC_, NC_, 0);
    // P[i][j] = scale * sum_c qT[i][c] kT[j][c]       M=2048 N=2048 K=512
    gemm_kernel<MODE_SCALE><<<dim3(16, 16, B_), 256, GSMEM>>>(
        qT, kT, p, nullptr, nullptr, C_, C_, N_, C_, NC_, NC_, NN_, 0);

    softmax_kernel<<<B_ * N_, 256>>>();

    // h2T[i][c] = sum_j P[i][j] v[c][j]               M=2048 N=512 K=2048
    gemm_kernel<MODE_NONE><<<dim3(4, 16, B_), 256, GSMEM>>>(
        p, v, h2T, nullptr, nullptr, N_, N_, C_, N_, NN_, NC_, NC_, 0);
    // out[o][n] = x + bp[o] + sum_c wp[o][c] h2T[n][c]  M=512 N=2048 K=512
    gemm_kernel<MODE_OUT><<<dim3(16, 4, B_), 256, GSMEM>>>(
        wp, h2T, out, bp, x, C_, C_, N_, C_, 0, NC_, NC_, NC_);
}

// round 8
// speedup vs baseline: 1.1714x; 1.0355x over previous
#include <cuda_runtime.h>
#include <cstdint>
#include <math.h>

#define B_   8
#define C_   512
#define N_   2048
#define GROUPS_ 32
#define CPG  16
#define EPSF 1e-6f

#define NC_ ((size_t)N_ * C_)      // 1048576
#define NN_ ((size_t)N_ * N_)      // 4194304

// ---------------- scratch ----------------
__device__ float g_hT [B_ * N_ * C_];          // groupnorm out, [b][n][c]
__device__ float g_qT [B_ * N_ * C_];          // [b][n][c]
__device__ float g_kT [B_ * N_ * C_];          // [b][n][c]
__device__ float g_v  [B_ * C_ * N_];          // [b][c][n]
__device__ float g_p  [(size_t)B_ * N_ * N_];  // [b][i][j]
__device__ float g_h2T[B_ * N_ * C_];          // [b][i][c]

// ---------------- helpers ----------------
__device__ __forceinline__ uint32_t smem_u32(const void* p) {
    uint32_t a;
    asm("{ .reg .u64 t; cvta.to.shared.u64 t, %1; cvt.u32.u64 %0, t; }" : "=r"(a) : "l"(p));
    return a;
}
__device__ __forceinline__ void cp_async16(uint32_t dst, const void* src) {
    asm volatile("cp.async.cg.shared.global [%0], [%1], 16;" :: "r"(dst), "l"(src));
}
#define CP_COMMIT() asm volatile("cp.async.commit_group;" ::: "memory")
#define CP_WAIT0()  asm volatile("cp.async.wait_group 0;" ::: "memory")

// mma.tf32 accepts raw fp32 bit patterns; tensor core truncates the mantissa.
__device__ __forceinline__ void mma_tf32(float* c, const uint32_t* a, const uint32_t* b) {
    asm volatile("mma.sync.aligned.m16n8k8.row.col.f32.tf32.tf32.f32 "
                 "{%0,%1,%2,%3}, {%4,%5,%6,%7}, {%8,%9}, {%0,%1,%2,%3};"
                 : "+f"(c[0]), "+f"(c[1]), "+f"(c[2]), "+f"(c[3])
                 : "r"(a[0]), "r"(a[1]), "r"(a[2]), "r"(a[3]), "r"(b[0]), "r"(b[1]));
}

// ---------------- GroupNorm (writes transposed hT[b][n][c] via smem tile) ----------------
__global__ __launch_bounds__(256) void groupnorm_kernel(const float* __restrict__ x,
                                                        const float* __restrict__ scale,
                                                        const float* __restrict__ bias) {
    int bg = blockIdx.x;
    int b = bg / GROUPS_, g = bg % GROUPS_;
    const float* xp  = x + ((size_t)b * C_ + (size_t)g * CPG) * N_;
    float*       hpT = g_hT + (size_t)b * NC_;
    int tid = threadIdx.x;
    const int total = CPG * N_;  // 32768

    float s = 0.f, ss = 0.f;
    for (int i = tid; i < total; i += 256) {
        float v = xp[i];
        s += v; ss += v * v;
    }
    __shared__ float rs[256], rq[256];
    rs[tid] = s; rq[tid] = ss;
    __syncthreads();
    for (int off = 128; off > 0; off >>= 1) {
        if (tid < off) { rs[tid] += rs[tid + off]; rq[tid] += rq[tid + off]; }
        __syncthreads();
    }
    float mean = rs[0] / (float)total;
    float var  = rq[0] / (float)total - mean * mean;
    float rinv = rsqrtf(var + EPSF);

    __shared__ float tile[128][17];
    for (int n0 = 0; n0 < N_; n0 += 128) {
        __syncthreads();
        int nl = tid & 127;
        int ch = tid >> 7;               // 0 or 1
        #pragma unroll
        for (int cp = 0; cp < 8; cp++) {
            int c = cp * 2 + ch;         // 0..15
            int cabs = g * CPG + c;
            tile[nl][c] = (xp[(size_t)c * N_ + n0 + nl] - mean) * rinv * scale[cabs] + bias[cabs];
        }
        __syncthreads();
        int row = tid >> 1;              // 0..127
        int half = (tid & 1) * 8;        // 0 or 8
        float* dst = hpT + (size_t)(n0 + row) * C_ + g * CPG + half;
        float4 o0, o1;
        o0.x = tile[row][half + 0]; o0.y = tile[row][half + 1];
        o0.z = tile[row][half + 2]; o0.w = tile[row][half + 3];
        o1.x = tile[row][half + 4]; o1.y = tile[row][half + 5];
        o1.z = tile[row][half + 6]; o1.w = tile[row][half + 7];
        *(float4*)(dst + 0) = o0;
        *(float4*)(dst + 4) = o1;
    }
}

// ---------------- tf32 mma.sync GEMM ----------------
// D[m][n] = sum_k A[m][k] * B[n][k], both K-major.
// Tile 128x128x32, 3-stage cp.async ring, cross-chunk register-fragment pipeline.
#define MODE_COLB  0
#define MODE_ROWB  1
#define MODE_SCALE 2
#define MODE_NONE  3
#define MODE_OUT   4

#define BK    32
#define PAD   36           // pitch % 32 == 4 -> banks (4m+k)%32 distinct over 8m x 4k
#define STAGEF (128 * PAD)
#define GSMEM  (3 * 2 * STAGEF * 4)   // 110592 bytes

template <int MODE, int NCK>
__global__ __launch_bounds__(256, 2)
void gemm_kernel(const float* __restrict__ A, const float* __restrict__ Bm,
                 float* __restrict__ D,
                 const float* __restrict__ bias, const float* __restrict__ resid,
                 int lda, int ldb, int ldd,
                 size_t a_bs, size_t b_bs, size_t d_bs, size_t r_bs) {
    extern __shared__ float smem[];   // [stage][A|B][STAGEF]

    int tid = threadIdx.x, lane = tid & 31, wid = tid >> 5;
    int warp_m = wid & 3;                // 4 warps over M
    int warp_n = wid >> 2;               // 2 warps over N

    int b  = blockIdx.z;
    int m0 = blockIdx.y * 128, n0 = blockIdx.x * 128;
    const float* Ab = A  + (size_t)b * a_bs;
    const float* Bb = Bm + (size_t)b * b_bs;
    float*       Db = D  + (size_t)b * d_bs;

    uint32_t sbase = smem_u32(smem);

    auto load_stage = [&](int stage, int k0) {
        uint32_t sa = sbase + (uint32_t)stage * (2u * STAGEF * 4u);
        uint32_t sb = sa + STAGEF * 4u;
        #pragma unroll
        for (int t = 0; t < 4; t++) {
            int idx = t * 256 + tid;
            int r = idx >> 3, c = idx & 7;
            uint32_t off = (uint32_t)(r * PAD + c * 4) * 4u;
            cp_async16(sa + off, Ab + (size_t)(m0 + r) * lda + k0 + c * 4);
            cp_async16(sb + off, Bb + (size_t)(n0 + r) * ldb + k0 + c * 4);
        }
    };

    int arow = warp_m * 32 + (lane >> 2);
    int brow = warp_n * 64 + (lane >> 2);
    int kq   = lane & 3;

    auto ldfragA = [&](const float* sa, int kbase, uint32_t fa[2][4]) {
        #pragma unroll
        for (int mt = 0; mt < 2; mt++) {
            const float* ap = sa + (arow + mt * 16) * PAD + kbase;
            fa[mt][0] = __float_as_uint(ap[0]);
            fa[mt][1] = __float_as_uint(ap[8 * PAD]);
            fa[mt][2] = __float_as_uint(ap[4]);
            fa[mt][3] = __float_as_uint(ap[8 * PAD + 4]);
        }
    };
    auto ldfragB = [&](const float* sb, int kbase, uint32_t fb[8][2]) {
        #pragma unroll
        for (int nt = 0; nt < 8; nt++) {
            const float* bp = sb + (brow + nt * 8) * PAD + kbase;
            fb[nt][0] = __float_as_uint(bp[0]);
            fb[nt][1] = __float_as_uint(bp[4]);
        }
    };

    float acc[2][8][4];
    #pragma unroll
    for (int i = 0; i < 2; i++)
        #pragma unroll
        for (int j = 0; j < 8; j++)
            #pragma unroll
            for (int t = 0; t < 4; t++) acc[i][j][t] = 0.f;

    uint32_t fA[2][2][4];
    uint32_t fB[2][8][2];

    // preloop: chunk0 resident + its kk=0 fragments in buf0; chunk1 in flight
    load_stage(0, 0);
    CP_COMMIT();
    CP_WAIT0();
    __syncthreads();
    load_stage(1, BK);
    CP_COMMIT();
    ldfragA(smem, kq, fA[0]);
    ldfragB(smem + STAGEF, kq, fB[0]);

    int stage = 0;
    #pragma unroll 1
    for (int ck = 0; ck < NCK; ck++) {
        CP_WAIT0();              // chunk ck+1 resident
        __syncthreads();         // visibility + protects stage (ck+2)%3 reuse

        int lst = stage + 2; if (lst >= 3) lst -= 3;
        if (ck + 2 < NCK) load_stage(lst, (ck + 2) * BK);
        CP_COMMIT();

        const float* sa = smem + (size_t)stage * 2 * STAGEF;
        const float* sb = sa + STAGEF;
        int nst = stage + 1; if (nst >= 3) nst -= 3;
        const float* xsa = smem + (size_t)nst * 2 * STAGEF;
        const float* xsb = xsa + STAGEF;

        #pragma unroll
        for (int kk = 0; kk < 4; kk++) {
            int cur = kk & 1, nxt = cur ^ 1;
            if (kk < 3) {
                ldfragA(sa, (kk + 1) * 8 + kq, fA[nxt]);
                ldfragB(sb, (kk + 1) * 8 + kq, fB[nxt]);
            } else {   // cross-chunk prefetch: next chunk's kk=0 (stage already resident)
                ldfragA(xsa, kq, fA[nxt]);
                ldfragB(xsb, kq, fB[nxt]);
            }
            #pragma unroll
            for (int mt = 0; mt < 2; mt++)
                #pragma unroll
                for (int nt = 0; nt < 8; nt++)
                    mma_tf32(acc[mt][nt], fA[cur][mt], fB[cur][nt]);
        }
        stage = nst;
    }

    // epilogue
    int rbase = m0 + warp_m * 32 + (lane >> 2);
    int cbase = n0 + warp_n * 64 + (lane & 3) * 2;
    #pragma unroll
    for (int mt = 0; mt < 2; mt++) {
        int r0 = rbase + mt * 16;
        int r1 = r0 + 8;
        float rb0 = 0.f, rb1 = 0.f;
        if (MODE == MODE_ROWB || MODE == MODE_OUT) { rb0 = bias[r0]; rb1 = bias[r1]; }
        #pragma unroll
        for (int nt = 0; nt < 8; nt++) {
            int cc = cbase + nt * 8;
            float e0 = acc[mt][nt][0], e1 = acc[mt][nt][1];
            float e2 = acc[mt][nt][2], e3 = acc[mt][nt][3];
            if (MODE == MODE_COLB) {
                float b0 = bias[cc], b1 = bias[cc + 1];
                e0 += b0; e1 += b1; e2 += b0; e3 += b1;
            } else if (MODE == MODE_SCALE) {
                const float scl = 0.044194173824159216f;
                e0 *= scl; e1 *= scl; e2 *= scl; e3 *= scl;
            } else if (MODE == MODE_ROWB) {
                e0 += rb0; e1 += rb0; e2 += rb1; e3 += rb1;
            } else if (MODE == MODE_OUT) {
                const float* rp0 = resid + (size_t)b * r_bs + (size_t)r0 * ldd + cc;
                const float* rp1 = resid + (size_t)b * r_bs + (size_t)r1 * ldd + cc;
                e0 += rb0 + rp0[0]; e1 += rb0 + rp0[1];
                e2 += rb1 + rp1[0]; e3 += rb1 + rp1[1];
            }
            float2 o0; o0.x = e0; o0.y = e1;
            float2 o1; o1.x = e2; o1.y = e3;
            *(float2*)(Db + (size_t)r0 * ldd + cc) = o0;
            *(float2*)(Db + (size_t)r1 * ldd + cc) = o1;
        }
    }
}

// ---------------- row softmax ----------------
__global__ __launch_bounds__(256) void softmax_kernel() {
    size_t row = blockIdx.x;
    float* p = g_p + row * N_;
    int tid = threadIdx.x;

    float v[8];
    float mx = -1e30f;
    #pragma unroll
    for (int j = 0; j < 8; j++) { v[j] = p[tid + j * 256]; mx = fmaxf(mx, v[j]); }

    __shared__ float red[256];
    red[tid] = mx; __syncthreads();
    for (int off = 128; off > 0; off >>= 1) {
        if (tid < off) red[tid] = fmaxf(red[tid], red[tid + off]);
        __syncthreads();
    }
    mx = red[0]; __syncthreads();

    float s = 0.f;
    #pragma unroll
    for (int j = 0; j < 8; j++) { v[j] = __expf(v[j] - mx); s += v[j]; }
    red[tid] = s; __syncthreads();
    for (int off = 128; off > 0; off >>= 1) {
        if (tid < off) red[tid] += red[tid + off];
        __syncthreads();
    }
    float rinv = 1.f / red[0];
    #pragma unroll
    for (int j = 0; j < 8; j++) p[tid + j * 256] = v[j] * rinv;
}

// ---------------- launch ----------------
extern "C" void kernel_launch(void* const* d_in, const int* in_sizes, int n_in,
                              void* d_out, int out_size) {
    const float* x  = (const float*)d_in[0];
    const float* gs = (const float*)d_in[1];
    const float* gb = (const float*)d_in[2];
    const float* wq = (const float*)d_in[3];
    const float* bq = (const float*)d_in[4];
    const float* wk = (const float*)d_in[5];
    const float* bk = (const float*)d_in[6];
    const float* wv = (const float*)d_in[7];
    const float* bv = (const float*)d_in[8];
    const float* wp = (const float*)d_in[9];
    const float* bp = (const float*)d_in[10];
    float* out = (float*)d_out;

    cudaFuncSetAttribute(gemm_kernel<MODE_COLB, 16>,  cudaFuncAttributeMaxDynamicSharedMemorySize, GSMEM);
    cudaFuncSetAttribute(gemm_kernel<MODE_ROWB, 16>,  cudaFuncAttributeMaxDynamicSharedMemorySize, GSMEM);
    cudaFuncSetAttribute(gemm_kernel<MODE_SCALE, 16>, cudaFuncAttributeMaxDynamicSharedMemorySize, GSMEM);
    cudaFuncSetAttribute(gemm_kernel<MODE_NONE, 64>,  cudaFuncAttributeMaxDynamicSharedMemorySize, GSMEM);
    cudaFuncSetAttribute(gemm_kernel<MODE_OUT, 16>,   cudaFuncAttributeMaxDynamicSharedMemorySize, GSMEM);

    float* hT  = nullptr; cudaGetSymbolAddress((void**)&hT,  g_hT);
    float* qT  = nullptr; cudaGetSymbolAddress((void**)&qT,  g_qT);
    float* kT  = nullptr; cudaGetSymbolAddress((void**)&kT,  g_kT);
    float* v   = nullptr; cudaGetSymbolAddress((void**)&v,   g_v);
    float* p   = nullptr; cudaGetSymbolAddress((void**)&p,   g_p);
    float* h2T = nullptr; cudaGetSymbolAddress((void**)&h2T, g_h2T);

    groupnorm_kernel<<<B_ * GROUPS_, 256>>>(x, gs, gb);

    // qT[n][o] = sum_c hT[n][c] wq[o][c] + bq[o]      M=2048 N=512 K=512
    gemm_kernel<MODE_COLB, 16><<<dim3(4, 16, B_), 256, GSMEM>>>(
        hT, wq, qT, bq, nullptr, C_, C_, C_, NC_, 0, NC_, 0);
    // kT
    gemm_kernel<MODE_COLB, 16><<<dim3(4, 16, B_), 256, GSMEM>>>(
        hT, wk, kT, bk, nullptr, C_, C_, C_, NC_, 0, NC_, 0);
    // v[o][n] = sum_c wv[o][c] hT[n][c] + bv[o]       M=512 N=2048 K=512
    gemm_kernel<MODE_ROWB, 16><<<dim3(16, 4, B_), 256, GSMEM>>>(
        wv, hT, v, bv, nullptr, C_, C_, N_, 0, NC_, NC_, 0);
    // P[i][j] = scale * sum_c qT[i][c] kT[j][c]       M=2048 N=2048 K=512
    gemm_kernel<MODE_SCALE, 16><<<dim3(16, 16, B_), 256, GSMEM>>>(
        qT, kT, p, nullptr, nullptr, C_, C_, N_, NC_, NC_, NN_, 0);

    softmax_kernel<<<B_ * N_, 256>>>();

    // h2T[i][c] = sum_j P[i][j] v[c][j]               M=2048 N=512 K=2048
    gemm_kernel<MODE_NONE, 64><<<dim3(4, 16, B_), 256, GSMEM>>>(
        p, v, h2T, nullptr, nullptr, N_, N_, C_, NN_, NC_, NC_, 0);
    // out[o][n] = x + bp[o] + sum_c wp[o][c] h2T[n][c]  M=512 N=2048 K=512
    gemm_kernel<MODE_OUT, 16><<<dim3(16, 4, B_), 256, GSMEM>>>(
        wp, h2T, out, bp, x, C_, C_, N_, 0, NC_, NC_, NC_);
}

// round 9
// speedup vs baseline: 1.2043x; 1.0281x over previous
#include <cuda_runtime.h>
#include <cstdint>
#include <math.h>

#define B_   8
#define C_   512
#define N_   2048
#define GROUPS_ 32
#define CPG  16
#define EPSF 1e-6f

#define NC_ ((size_t)N_ * C_)      // 1048576
#define NN_ ((size_t)N_ * N_)      // 4194304

// ---------------- scratch ----------------
__device__ float g_hT [B_ * N_ * C_];          // groupnorm out, [b][n][c]
__device__ float g_qT [B_ * N_ * C_];          // [b][n][c]
__device__ float g_kT [B_ * N_ * C_];          // [b][n][c]
__device__ float g_v  [B_ * C_ * N_];          // [b][c][n]
__device__ float g_p  [(size_t)B_ * N_ * N_];  // [b][i][j]
__device__ float g_h2T[B_ * N_ * C_];          // [b][i][c]

// ---------------- helpers ----------------
__device__ __forceinline__ uint32_t smem_u32(const void* p) {
    uint32_t a;
    asm("{ .reg .u64 t; cvta.to.shared.u64 t, %1; cvt.u32.u64 %0, t; }" : "=r"(a) : "l"(p));
    return a;
}
__device__ __forceinline__ void cp_async16(uint32_t dst, const void* src) {
    asm volatile("cp.async.cg.shared.global [%0], [%1], 16;" :: "r"(dst), "l"(src));
}
#define CP_COMMIT() asm volatile("cp.async.commit_group;" ::: "memory")
#define CP_WAIT0()  asm volatile("cp.async.wait_group 0;" ::: "memory")

// mma.tf32 accepts raw fp32 bit patterns; tensor core truncates the mantissa.
__device__ __forceinline__ void mma_tf32(float* c, const uint32_t* a, const uint32_t* b) {
    asm volatile("mma.sync.aligned.m16n8k8.row.col.f32.tf32.tf32.f32 "
                 "{%0,%1,%2,%3}, {%4,%5,%6,%7}, {%8,%9}, {%0,%1,%2,%3};"
                 : "+f"(c[0]), "+f"(c[1]), "+f"(c[2]), "+f"(c[3])
                 : "r"(a[0]), "r"(a[1]), "r"(a[2]), "r"(a[3]), "r"(b[0]), "r"(b[1]));
}

// ---------------- GroupNorm (writes transposed hT[b][n][c] via smem tile) ----------------
__global__ __launch_bounds__(256) void groupnorm_kernel(const float* __restrict__ x,
                                                        const float* __restrict__ scale,
                                                        const float* __restrict__ bias) {
    int bg = blockIdx.x;
    int b = bg / GROUPS_, g = bg % GROUPS_;
    const float* xp  = x + ((size_t)b * C_ + (size_t)g * CPG) * N_;
    float*       hpT = g_hT + (size_t)b * NC_;
    int tid = threadIdx.x;
    const int total = CPG * N_;  // 32768

    float s = 0.f, ss = 0.f;
    for (int i = tid; i < total; i += 256) {
        float v = xp[i];
        s += v; ss += v * v;
    }
    __shared__ float rs[256], rq[256];
    rs[tid] = s; rq[tid] = ss;
    __syncthreads();
    for (int off = 128; off > 0; off >>= 1) {
        if (tid < off) { rs[tid] += rs[tid + off]; rq[tid] += rq[tid + off]; }
        __syncthreads();
    }
    float mean = rs[0] / (float)total;
    float var  = rq[0] / (float)total - mean * mean;
    float rinv = rsqrtf(var + EPSF);

    __shared__ float tile[128][17];
    for (int n0 = 0; n0 < N_; n0 += 128) {
        __syncthreads();
        int nl = tid & 127;
        int ch = tid >> 7;               // 0 or 1
        #pragma unroll
        for (int cp = 0; cp < 8; cp++) {
            int c = cp * 2 + ch;         // 0..15
            int cabs = g * CPG + c;
            tile[nl][c] = (xp[(size_t)c * N_ + n0 + nl] - mean) * rinv * scale[cabs] + bias[cabs];
        }
        __syncthreads();
        int row = tid >> 1;              // 0..127
        int half = (tid & 1) * 8;        // 0 or 8
        float* dst = hpT + (size_t)(n0 + row) * C_ + g * CPG + half;
        float4 o0, o1;
        o0.x = tile[row][half + 0]; o0.y = tile[row][half + 1];
        o0.z = tile[row][half + 2]; o0.w = tile[row][half + 3];
        o1.x = tile[row][half + 4]; o1.y = tile[row][half + 5];
        o1.z = tile[row][half + 6]; o1.w = tile[row][half + 7];
        *(float4*)(dst + 0) = o0;
        *(float4*)(dst + 4) = o1;
    }
}

// ---------------- tf32 mma.sync GEMM ----------------
// D[m][n] = sum_k A[m][k] * B[n][k], both K-major.
// Tile 128x128x32, 3-stage cp.async ring, cross-chunk register-fragment pipeline.
// MODE_COLB supports a dual launch: blockIdx.z >= gridDim.z/2 selects (Bm2, bias2, D2).
#define MODE_COLB  0
#define MODE_ROWB  1
#define MODE_SCALE 2
#define MODE_NONE  3
#define MODE_OUT   4

#define BK    32
#define PAD   36           // pitch % 32 == 4 -> banks (4m+k)%32 distinct over 8m x 4k
#define STAGEF (128 * PAD)
#define GSMEM  (3 * 2 * STAGEF * 4)   // 110592 bytes

template <int MODE, int NCK>
__global__ __launch_bounds__(256, 2)
void gemm_kernel(const float* __restrict__ A, const float* __restrict__ Bm,
                 float* __restrict__ D,
                 const float* __restrict__ bias, const float* __restrict__ resid,
                 const float* __restrict__ Bm2, const float* __restrict__ bias2,
                 float* __restrict__ D2,
                 int lda, int ldb, int ldd,
                 size_t a_bs, size_t b_bs, size_t d_bs, size_t r_bs) {
    extern __shared__ float smem[];   // [stage][A|B][STAGEF]

    int tid = threadIdx.x, lane = tid & 31, wid = tid >> 5;
    int warp_m = wid & 3;                // 4 warps over M
    int warp_n = wid >> 2;               // 2 warps over N

    int b = blockIdx.z;
    const float* Bsel = Bm;
    const float* bsel = bias;
    float*       Dsel = D;
    if (MODE == MODE_COLB) {
        int half = gridDim.z >> 1;
        if ((int)blockIdx.z >= half) {
            b = blockIdx.z - half;
            Bsel = Bm2; bsel = bias2; Dsel = D2;
        }
    }

    int m0 = blockIdx.y * 128, n0 = blockIdx.x * 128;
    const float* Ab = A    + (size_t)b * a_bs;
    const float* Bb = Bsel + (size_t)b * b_bs;
    float*       Db = Dsel + (size_t)b * d_bs;

    uint32_t sbase = smem_u32(smem);

    auto load_stage = [&](int stage, int k0) {
        uint32_t sa = sbase + (uint32_t)stage * (2u * STAGEF * 4u);
        uint32_t sb = sa + STAGEF * 4u;
        #pragma unroll
        for (int t = 0; t < 4; t++) {
            int idx = t * 256 + tid;
            int r = idx >> 3, c = idx & 7;
            uint32_t off = (uint32_t)(r * PAD + c * 4) * 4u;
            cp_async16(sa + off, Ab + (size_t)(m0 + r) * lda + k0 + c * 4);
            cp_async16(sb + off, Bb + (size_t)(n0 + r) * ldb + k0 + c * 4);
        }
    };

    int arow = warp_m * 32 + (lane >> 2);
    int brow = warp_n * 64 + (lane >> 2);
    int kq   = lane & 3;

    auto ldfragA = [&](const float* sa, int kbase, uint32_t fa[2][4]) {
        #pragma unroll
        for (int mt = 0; mt < 2; mt++) {
            const float* ap = sa + (arow + mt * 16) * PAD + kbase;
            fa[mt][0] = __float_as_uint(ap[0]);
            fa[mt][1] = __float_as_uint(ap[8 * PAD]);
            fa[mt][2] = __float_as_uint(ap[4]);
            fa[mt][3] = __float_as_uint(ap[8 * PAD + 4]);
        }
    };
    auto ldfragB = [&](const float* sb, int kbase, uint32_t fb[8][2]) {
        #pragma unroll
        for (int nt = 0; nt < 8; nt++) {
            const float* bp = sb + (brow + nt * 8) * PAD + kbase;
            fb[nt][0] = __float_as_uint(bp[0]);
            fb[nt][1] = __float_as_uint(bp[4]);
        }
    };

    float acc[2][8][4];
    #pragma unroll
    for (int i = 0; i < 2; i++)
        #pragma unroll
        for (int j = 0; j < 8; j++)
            #pragma unroll
            for (int t = 0; t < 4; t++) acc[i][j][t] = 0.f;

    uint32_t fA[2][2][4];
    uint32_t fB[2][8][2];

    // preloop: chunk0 resident + its kk=0 fragments in buf0; chunk1 in flight
    load_stage(0, 0);
    CP_COMMIT();
    CP_WAIT0();
    __syncthreads();
    load_stage(1, BK);
    CP_COMMIT();
    ldfragA(smem, kq, fA[0]);
    ldfragB(smem + STAGEF, kq, fB[0]);

    int stage = 0;
    #pragma unroll 1
    for (int ck = 0; ck < NCK; ck++) {
        CP_WAIT0();              // chunk ck+1 resident
        __syncthreads();         // visibility + protects stage (ck+2)%3 reuse

        int lst = stage + 2; if (lst >= 3) lst -= 3;
        if (ck + 2 < NCK) load_stage(lst, (ck + 2) * BK);
        CP_COMMIT();

        const float* sa = smem + (size_t)stage * 2 * STAGEF;
        const float* sb = sa + STAGEF;
        int nst = stage + 1; if (nst >= 3) nst -= 3;
        const float* xsa = smem + (size_t)nst * 2 * STAGEF;
        const float* xsb = xsa + STAGEF;

        #pragma unroll
        for (int kk = 0; kk < 4; kk++) {
            int cur = kk & 1, nxt = cur ^ 1;
            if (kk < 3) {
                ldfragA(sa, (kk + 1) * 8 + kq, fA[nxt]);
                ldfragB(sb, (kk + 1) * 8 + kq, fB[nxt]);
            } else {   // cross-chunk prefetch: next chunk's kk=0 (stage already resident)
                ldfragA(xsa, kq, fA[nxt]);
                ldfragB(xsb, kq, fB[nxt]);
            }
            #pragma unroll
            for (int mt = 0; mt < 2; mt++)
                #pragma unroll
                for (int nt = 0; nt < 8; nt++)
                    mma_tf32(acc[mt][nt], fA[cur][mt], fB[cur][nt]);
        }
        stage = nst;
    }

    // epilogue
    int rbase = m0 + warp_m * 32 + (lane >> 2);
    int cbase = n0 + warp_n * 64 + (lane & 3) * 2;
    #pragma unroll
    for (int mt = 0; mt < 2; mt++) {
        int r0 = rbase + mt * 16;
        int r1 = r0 + 8;
        float rb0 = 0.f, rb1 = 0.f;
        if (MODE == MODE_ROWB || MODE == MODE_OUT) { rb0 = bsel[r0]; rb1 = bsel[r1]; }
        #pragma unroll
        for (int nt = 0; nt < 8; nt++) {
            int cc = cbase + nt * 8;
            float e0 = acc[mt][nt][0], e1 = acc[mt][nt][1];
            float e2 = acc[mt][nt][2], e3 = acc[mt][nt][3];
            if (MODE == MODE_COLB) {
                float b0 = bsel[cc], b1 = bsel[cc + 1];
                e0 += b0; e1 += b1; e2 += b0; e3 += b1;
            } else if (MODE == MODE_SCALE) {
                const float scl = 0.044194173824159216f;
                e0 *= scl; e1 *= scl; e2 *= scl; e3 *= scl;
            } else if (MODE == MODE_ROWB) {
                e0 += rb0; e1 += rb0; e2 += rb1; e3 += rb1;
            } else if (MODE == MODE_OUT) {
                const float* rp0 = resid + (size_t)b * r_bs + (size_t)r0 * ldd + cc;
                const float* rp1 = resid + (size_t)b * r_bs + (size_t)r1 * ldd + cc;
                e0 += rb0 + rp0[0]; e1 += rb0 + rp0[1];
                e2 += rb1 + rp1[0]; e3 += rb1 + rp1[1];
            }
            float2 o0; o0.x = e0; o0.y = e1;
            float2 o1; o1.x = e2; o1.y = e3;
            *(float2*)(Db + (size_t)r0 * ldd + cc) = o0;
            *(float2*)(Db + (size_t)r1 * ldd + cc) = o1;
        }
    }
}

// ---------------- row softmax (vectorized) ----------------
__global__ __launch_bounds__(256) void softmax_kernel() {
    size_t row = blockIdx.x;
    float4* p4 = (float4*)(g_p + row * N_);
    int tid = threadIdx.x;

    float4 va = p4[tid];
    float4 vb = p4[tid + 256];
    float mx = fmaxf(fmaxf(fmaxf(va.x, va.y), fmaxf(va.z, va.w)),
                     fmaxf(fmaxf(vb.x, vb.y), fmaxf(vb.z, vb.w)));

    __shared__ float red[256];
    red[tid] = mx; __syncthreads();
    for (int off = 128; off > 0; off >>= 1) {
        if (tid < off) red[tid] = fmaxf(red[tid], red[tid + off]);
        __syncthreads();
    }
    mx = red[0]; __syncthreads();

    va.x = __expf(va.x - mx); va.y = __expf(va.y - mx);
    va.z = __expf(va.z - mx); va.w = __expf(va.w - mx);
    vb.x = __expf(vb.x - mx); vb.y = __expf(vb.y - mx);
    vb.z = __expf(vb.z - mx); vb.w = __expf(vb.w - mx);
    float s = (va.x + va.y + va.z + va.w) + (vb.x + vb.y + vb.z + vb.w);

    red[tid] = s; __syncthreads();
    for (int off = 128; off > 0; off >>= 1) {
        if (tid < off) red[tid] += red[tid + off];
        __syncthreads();
    }
    float rinv = 1.f / red[0];
    va.x *= rinv; va.y *= rinv; va.z *= rinv; va.w *= rinv;
    vb.x *= rinv; vb.y *= rinv; vb.z *= rinv; vb.w *= rinv;
    p4[tid] = va;
    p4[tid + 256] = vb;
}

// ---------------- launch ----------------
extern "C" void kernel_launch(void* const* d_in, const int* in_sizes, int n_in,
                              void* d_out, int out_size) {
    const float* x  = (const float*)d_in[0];
    const float* gs = (const float*)d_in[1];
    const float* gb = (const float*)d_in[2];
    const float* wq = (const float*)d_in[3];
    const float* bq = (const float*)d_in[4];
    const float* wk = (const float*)d_in[5];
    const float* bk = (const float*)d_in[6];
    const float* wv = (const float*)d_in[7];
    const float* bv = (const float*)d_in[8];
    const float* wp = (const float*)d_in[9];
    const float* bp = (const float*)d_in[10];
    float* out = (float*)d_out;

    cudaFuncSetAttribute(gemm_kernel<MODE_COLB, 16>,  cudaFuncAttributeMaxDynamicSharedMemorySize, GSMEM);
    cudaFuncSetAttribute(gemm_kernel<MODE_ROWB, 16>,  cudaFuncAttributeMaxDynamicSharedMemorySize, GSMEM);
    cudaFuncSetAttribute(gemm_kernel<MODE_SCALE, 16>, cudaFuncAttributeMaxDynamicSharedMemorySize, GSMEM);
    cudaFuncSetAttribute(gemm_kernel<MODE_NONE, 64>,  cudaFuncAttributeMaxDynamicSharedMemorySize, GSMEM);
    cudaFuncSetAttribute(gemm_kernel<MODE_OUT, 16>,   cudaFuncAttributeMaxDynamicSharedMemorySize, GSMEM);

    float* hT  = nullptr; cudaGetSymbolAddress((void**)&hT,  g_hT);
    float* qT  = nullptr; cudaGetSymbolAddress((void**)&qT,  g_qT);
    float* kT  = nullptr; cudaGetSymbolAddress((void**)&kT,  g_kT);
    float* v   = nullptr; cudaGetSymbolAddress((void**)&v,   g_v);
    float* p   = nullptr; cudaGetSymbolAddress((void**)&p,   g_p);
    float* h2T = nullptr; cudaGetSymbolAddress((void**)&h2T, g_h2T);

    groupnorm_kernel<<<B_ * GROUPS_, 256>>>(x, gs, gb);

    // merged qT+kT: z<8 -> (wq,bq,qT); z>=8 -> (wk,bk,kT).  M=2048 N=512 K=512 each
    gemm_kernel<MODE_COLB, 16><<<dim3(4, 16, 2 * B_), 256, GSMEM>>>(
        hT, wq, qT, bq, nullptr, wk, bk, kT, C_, C_, C_, NC_, 0, NC_, 0);
    // v[o][n] = sum_c wv[o][c] hT[n][c] + bv[o]       M=512 N=2048 K=512
    gemm_kernel<MODE_ROWB, 16><<<dim3(16, 4, B_), 256, GSMEM>>>(
        wv, hT, v, bv, nullptr, nullptr, nullptr, nullptr, C_, C_, N_, 0, NC_, NC_, 0);
    // P[i][j] = scale * sum_c qT[i][c] kT[j][c]       M=2048 N=2048 K=512
    gemm_kernel<MODE_SCALE, 16><<<dim3(16, 16, B_), 256, GSMEM>>>(
        qT, kT, p, nullptr, nullptr, nullptr, nullptr, nullptr, C_, C_, N_, NC_, NC_, NN_, 0);

    softmax_kernel<<<B_ * N_, 256>>>();

    // h2T[i][c] = sum_j P[i][j] v[c][j]               M=2048 N=512 K=2048
    gemm_kernel<MODE_NONE, 64><<<dim3(4, 16, B_), 256, GSMEM>>>(
        p, v, h2T, nullptr, nullptr, nullptr, nullptr, nullptr, N_, N_, C_, NN_, NC_, NC_, 0);
    // out[o][n] = x + bp[o] + sum_c wp[o][c] h2T[n][c]  M=512 N=2048 K=512
    gemm_kernel<MODE_OUT, 16><<<dim3(16, 4, B_), 256, GSMEM>>>(
        wp, h2T, out, bp, x, nullptr, nullptr, nullptr, C_, C_, N_, 0, NC_, NC_, NC_);
}

// round 10
// speedup vs baseline: 2.0618x; 1.7120x over previous
#include <cuda_runtime.h>
#include <cuda_fp16.h>
#include <cstdint>
#include <math.h>

#define B_   8
#define C_   512
#define N_   2048
#define GROUPS_ 32
#define CPG  16
#define EPSF 1e-6f

#define NC_ ((size_t)N_ * C_)      // 1048576
#define NN_ ((size_t)N_ * N_)      // 4194304

// ---------------- scratch ----------------
__device__ __half g_hTh [B_ * N_ * C_];          // groupnorm out, [b][n][c] half
__device__ __half g_qTh [B_ * N_ * C_];          // [b][n][c]
__device__ __half g_kTh [B_ * N_ * C_];          // [b][n][c]
__device__ __half g_vh  [B_ * C_ * N_];          // [b][c][n]
__device__ float  g_p   [(size_t)B_ * N_ * N_];  // logits fp32 [b][i][j]
__device__ __half g_ph  [(size_t)B_ * N_ * N_];  // probs half [b][i][j]
__device__ __half g_h2Th[B_ * N_ * C_];          // [b][i][c]
__device__ __half g_wh  [4 * C_ * C_];           // wq,wk,wv,wp as half

// ---------------- helpers ----------------
__device__ __forceinline__ uint32_t smem_u32(const void* p) {
    uint32_t a;
    asm("{ .reg .u64 t; cvta.to.shared.u64 t, %1; cvt.u32.u64 %0, t; }" : "=r"(a) : "l"(p));
    return a;
}
__device__ __forceinline__ void cp_async16(uint32_t dst, const void* src) {
    asm volatile("cp.async.cg.shared.global [%0], [%1], 16;" :: "r"(dst), "l"(src));
}
#define CP_COMMIT() asm volatile("cp.async.commit_group;" ::: "memory")
#define CP_WAIT0()  asm volatile("cp.async.wait_group 0;" ::: "memory")

__device__ __forceinline__ void mma_f16(float* c, const uint32_t* a, const uint32_t* b) {
    asm volatile("mma.sync.aligned.m16n8k16.row.col.f32.f16.f16.f32 "
                 "{%0,%1,%2,%3}, {%4,%5,%6,%7}, {%8,%9}, {%0,%1,%2,%3};"
                 : "+f"(c[0]), "+f"(c[1]), "+f"(c[2]), "+f"(c[3])
                 : "r"(a[0]), "r"(a[1]), "r"(a[2]), "r"(a[3]), "r"(b[0]), "r"(b[1]));
}

// ---------------- weight fp32 -> fp16 ----------------
__global__ __launch_bounds__(256) void cvt_w_kernel(const float* __restrict__ wq,
                                                    const float* __restrict__ wk,
                                                    const float* __restrict__ wv,
                                                    const float* __restrict__ wp) {
    const float* src = (blockIdx.y == 0) ? wq : (blockIdx.y == 1) ? wk
                       : (blockIdx.y == 2) ? wv : wp;
    __half* dst = g_wh + (size_t)blockIdx.y * C_ * C_;
    int i = (blockIdx.x * 256 + threadIdx.x) * 4;     // C_*C_/4 = 65536 float4
    float4 v = *(const float4*)(src + i);
    __half2 h0 = __floats2half2_rn(v.x, v.y);
    __half2 h1 = __floats2half2_rn(v.z, v.w);
    *(uint2*)(dst + i) = make_uint2(*(uint32_t*)&h0, *(uint32_t*)&h1);
}

// ---------------- GroupNorm (writes transposed half hT[b][n][c]) ----------------
__global__ __launch_bounds__(256) void groupnorm_kernel(const float* __restrict__ x,
                                                        const float* __restrict__ scale,
                                                        const float* __restrict__ bias) {
    int bg = blockIdx.x;
    int b = bg / GROUPS_, g = bg % GROUPS_;
    const float* xp  = x + ((size_t)b * C_ + (size_t)g * CPG) * N_;
    __half*      hpT = g_hTh + (size_t)b * NC_;
    int tid = threadIdx.x;
    const int total = CPG * N_;  // 32768

    float s = 0.f, ss = 0.f;
    for (int i = tid; i < total; i += 256) {
        float v = xp[i];
        s += v; ss += v * v;
    }
    __shared__ float rs[256], rq[256];
    rs[tid] = s; rq[tid] = ss;
    __syncthreads();
    for (int off = 128; off > 0; off >>= 1) {
        if (tid < off) { rs[tid] += rs[tid + off]; rq[tid] += rq[tid + off]; }
        __syncthreads();
    }
    float mean = rs[0] / (float)total;
    float var  = rq[0] / (float)total - mean * mean;
    float rinv = rsqrtf(var + EPSF);

    __shared__ float tile[128][17];
    for (int n0 = 0; n0 < N_; n0 += 128) {
        __syncthreads();
        int nl = tid & 127;
        int ch = tid >> 7;
        #pragma unroll
        for (int cp = 0; cp < 8; cp++) {
            int c = cp * 2 + ch;
            int cabs = g * CPG + c;
            tile[nl][c] = (xp[(size_t)c * N_ + n0 + nl] - mean) * rinv * scale[cabs] + bias[cabs];
        }
        __syncthreads();
        int row = tid >> 1;
        int half = (tid & 1) * 8;
        __half* dst = hpT + (size_t)(n0 + row) * C_ + g * CPG + half;
        __half2 h0 = __floats2half2_rn(tile[row][half + 0], tile[row][half + 1]);
        __half2 h1 = __floats2half2_rn(tile[row][half + 2], tile[row][half + 3]);
        __half2 h2 = __floats2half2_rn(tile[row][half + 4], tile[row][half + 5]);
        __half2 h3 = __floats2half2_rn(tile[row][half + 6], tile[row][half + 7]);
        *(uint4*)dst = make_uint4(*(uint32_t*)&h0, *(uint32_t*)&h1,
                                  *(uint32_t*)&h2, *(uint32_t*)&h3);
    }
}

// ---------------- fp16 mma.sync GEMM ----------------
// D[m][n] = sum_k A[m][k] * B[n][k], both K-major half.
// Tile 128x128x64(half), 3-stage cp.async ring, cross-chunk fragment pipeline.
#define MODE_COLB  0   // + bias[col], D half      (qT / kT dual)
#define MODE_ROWB  1   // + bias[row], D half      (v)
#define MODE_SCALE 2   // * scale,     D float     (QK logits)
#define MODE_NONE  3   //              D half      (PV)
#define MODE_OUT   4   // + bias[row] + resid, D float

#define BKH    64            // K-chunk in halves
#define PADH   72            // row pitch halves; word bank (36m + t) % 32 = (4m+t)%32 distinct
#define STAGEH (128 * PADH)  // halves per operand per stage
#define GSMEM  (3 * 2 * STAGEH * 2)   // 110592 bytes

template <int MODE, int NCK>
__global__ __launch_bounds__(256, 2)
void gemm_kernel(const __half* __restrict__ A, const __half* __restrict__ Bm,
                 void* __restrict__ Dv,
                 const float* __restrict__ bias, const float* __restrict__ resid,
                 const __half* __restrict__ Bm2, const float* __restrict__ bias2,
                 void* __restrict__ Dv2,
                 int lda, int ldb, int ldd,
                 size_t a_bs, size_t b_bs, size_t d_bs, size_t r_bs) {
    extern __shared__ __half smem[];   // [stage][A|B][STAGEH]

    int tid = threadIdx.x, lane = tid & 31, wid = tid >> 5;
    int warp_m = wid & 3;
    int warp_n = wid >> 2;

    int b = blockIdx.z;
    const __half* Bsel = Bm;
    const float*  bsel = bias;
    void*         Dsel = Dv;
    if (MODE == MODE_COLB) {
        int half = gridDim.z >> 1;
        if ((int)blockIdx.z >= half) {
            b = blockIdx.z - half;
            Bsel = Bm2; bsel = bias2; Dsel = Dv2;
        }
    }

    int m0 = blockIdx.y * 128, n0 = blockIdx.x * 128;
    const __half* Ab = A    + (size_t)b * a_bs;
    const __half* Bb = Bsel + (size_t)b * b_bs;

    uint32_t sbase = smem_u32(smem);

    auto load_stage = [&](int stage, int k0) {
        uint32_t sa = sbase + (uint32_t)stage * (2u * STAGEH * 2u);
        uint32_t sb = sa + STAGEH * 2u;
        #pragma unroll
        for (int t = 0; t < 4; t++) {
            int idx = t * 256 + tid;            // 1024 16B-vectors per operand
            int r = idx >> 3, c = idx & 7;
            uint32_t off = (uint32_t)(r * PADH + c * 8) * 2u;
            cp_async16(sa + off, Ab + (size_t)(m0 + r) * lda + k0 + c * 8);
            cp_async16(sb + off, Bb + (size_t)(n0 + r) * ldb + k0 + c * 8);
        }
    };

    int arow = warp_m * 32 + (lane >> 2);
    int brow = warp_n * 64 + (lane >> 2);
    int kq2  = (lane & 3) * 2;                  // half offset within k16

    auto ldfragA = [&](const __half* sa, int kbase, uint32_t fa[2][4]) {
        #pragma unroll
        for (int mt = 0; mt < 2; mt++) {
            const __half* ap = sa + (arow + mt * 16) * PADH + kbase;
            fa[mt][0] = *(const uint32_t*)(ap);
            fa[mt][1] = *(const uint32_t*)(ap + 8 * PADH);
            fa[mt][2] = *(const uint32_t*)(ap + 8);
            fa[mt][3] = *(const uint32_t*)(ap + 8 * PADH + 8);
        }
    };
    auto ldfragB = [&](const __half* sb, int kbase, uint32_t fb[8][2]) {
        #pragma unroll
        for (int nt = 0; nt < 8; nt++) {
            const __half* bp = sb + (brow + nt * 8) * PADH + kbase;
            fb[nt][0] = *(const uint32_t*)(bp);
            fb[nt][1] = *(const uint32_t*)(bp + 8);
        }
    };

    float acc[2][8][4];
    #pragma unroll
    for (int i = 0; i < 2; i++)
        #pragma unroll
        for (int j = 0; j < 8; j++)
            #pragma unroll
            for (int t = 0; t < 4; t++) acc[i][j][t] = 0.f;

    uint32_t fA[2][2][4];
    uint32_t fB[2][8][2];

    load_stage(0, 0);
    CP_COMMIT();
    CP_WAIT0();
    __syncthreads();
    load_stage(1, BKH);
    CP_COMMIT();
    ldfragA(smem, kq2, fA[0]);
    ldfragB(smem + STAGEH, kq2, fB[0]);

    int stage = 0;
    #pragma unroll 1
    for (int ck = 0; ck < NCK; ck++) {
        CP_WAIT0();
        __syncthreads();

        int lst = stage + 2; if (lst >= 3) lst -= 3;
        if (ck + 2 < NCK) load_stage(lst, (ck + 2) * BKH);
        CP_COMMIT();

        const __half* sa = smem + (size_t)stage * 2 * STAGEH;
        const __half* sb = sa + STAGEH;
        int nst = stage + 1; if (nst >= 3) nst -= 3;
        const __half* xsa = smem + (size_t)nst * 2 * STAGEH;
        const __half* xsb = xsa + STAGEH;

        #pragma unroll
        for (int kk = 0; kk < 4; kk++) {        // 4 x k16 = 64 halves
            int cur = kk & 1, nxt = cur ^ 1;
            if (kk < 3) {
                ldfragA(sa, (kk + 1) * 16 + kq2, fA[nxt]);
                ldfragB(sb, (kk + 1) * 16 + kq2, fB[nxt]);
            } else {
                ldfragA(xsa, kq2, fA[nxt]);
                ldfragB(xsb, kq2, fB[nxt]);
            }
            #pragma unroll
            for (int mt = 0; mt < 2; mt++)
                #pragma unroll
                for (int nt = 0; nt < 8; nt++)
                    mma_f16(acc[mt][nt], fA[cur][mt], fB[cur][nt]);
        }
        stage = nst;
    }

    // epilogue
    constexpr bool HALF_OUT = (MODE == MODE_COLB || MODE == MODE_ROWB || MODE == MODE_NONE);
    int rbase = m0 + warp_m * 32 + (lane >> 2);
    int cbase = n0 + warp_n * 64 + (lane & 3) * 2;
    #pragma unroll
    for (int mt = 0; mt < 2; mt++) {
        int r0 = rbase + mt * 16;
        int r1 = r0 + 8;
        float rb0 = 0.f, rb1 = 0.f;
        if (MODE == MODE_ROWB || MODE == MODE_OUT) { rb0 = bsel[r0]; rb1 = bsel[r1]; }
        #pragma unroll
        for (int nt = 0; nt < 8; nt++) {
            int cc = cbase + nt * 8;
            float e0 = acc[mt][nt][0], e1 = acc[mt][nt][1];
            float e2 = acc[mt][nt][2], e3 = acc[mt][nt][3];
            if (MODE == MODE_COLB) {
                float b0 = bsel[cc], b1 = bsel[cc + 1];
                e0 += b0; e1 += b1; e2 += b0; e3 += b1;
            } else if (MODE == MODE_SCALE) {
                const float scl = 0.044194173824159216f;
                e0 *= scl; e1 *= scl; e2 *= scl; e3 *= scl;
            } else if (MODE == MODE_ROWB) {
                e0 += rb0; e1 += rb0; e2 += rb1; e3 += rb1;
            } else if (MODE == MODE_OUT) {
                const float* rp0 = resid + (size_t)b * r_bs + (size_t)r0 * ldd + cc;
                const float* rp1 = resid + (size_t)b * r_bs + (size_t)r1 * ldd + cc;
                e0 += rb0 + rp0[0]; e1 += rb0 + rp0[1];
                e2 += rb1 + rp1[0]; e3 += rb1 + rp1[1];
            }
            if (HALF_OUT) {
                __half* Dh = (__half*)Dsel + (size_t)b * d_bs;
                __half2 h0 = __floats2half2_rn(e0, e1);
                __half2 h1 = __floats2half2_rn(e2, e3);
                *(__half2*)(Dh + (size_t)r0 * ldd + cc) = h0;
                *(__half2*)(Dh + (size_t)r1 * ldd + cc) = h1;
            } else {
                float* Df = (float*)Dsel + (size_t)b * d_bs;
                float2 o0; o0.x = e0; o0.y = e1;
                float2 o1; o1.x = e2; o1.y = e3;
                *(float2*)(Df + (size_t)r0 * ldd + cc) = o0;
                *(float2*)(Df + (size_t)r1 * ldd + cc) = o1;
            }
        }
    }
}

// ---------------- row softmax: fp32 logits -> half probs ----------------
__global__ __launch_bounds__(256) void softmax_kernel() {
    size_t row = blockIdx.x;
    const float4* p4 = (const float4*)(g_p + row * N_);
    uint2* o4 = (uint2*)(g_ph + row * N_);      // 4 halves per uint2
    int tid = threadIdx.x;

    float4 va = p4[tid];
    float4 vb = p4[tid + 256];
    float mx = fmaxf(fmaxf(fmaxf(va.x, va.y), fmaxf(va.z, va.w)),
                     fmaxf(fmaxf(vb.x, vb.y), fmaxf(vb.z, vb.w)));

    __shared__ float red[256];
    red[tid] = mx; __syncthreads();
    for (int off = 128; off > 0; off >>= 1) {
        if (tid < off) red[tid] = fmaxf(red[tid], red[tid + off]);
        __syncthreads();
    }
    mx = red[0]; __syncthreads();

    va.x = __expf(va.x - mx); va.y = __expf(va.y - mx);
    va.z = __expf(va.z - mx); va.w = __expf(va.w - mx);
    vb.x = __expf(vb.x - mx); vb.y = __expf(vb.y - mx);
    vb.z = __expf(vb.z - mx); vb.w = __expf(vb.w - mx);
    float s = (va.x + va.y + va.z + va.w) + (vb.x + vb.y + vb.z + vb.w);

    red[tid] = s; __syncthreads();
    for (int off = 128; off > 0; off >>= 1) {
        if (tid < off) red[tid] += red[tid + off];
        __syncthreads();
    }
    float rinv = 1.f / red[0];

    __half2 a0 = __floats2half2_rn(va.x * rinv, va.y * rinv);
    __half2 a1 = __floats2half2_rn(va.z * rinv, va.w * rinv);
    __half2 b0 = __floats2half2_rn(vb.x * rinv, vb.y * rinv);
    __half2 b1 = __floats2half2_rn(vb.z * rinv, vb.w * rinv);
    o4[tid]       = make_uint2(*(uint32_t*)&a0, *(uint32_t*)&a1);
    o4[tid + 256] = make_uint2(*(uint32_t*)&b0, *(uint32_t*)&b1);
}

// ---------------- launch ----------------
extern "C" void kernel_launch(void* const* d_in, const int* in_sizes, int n_in,
                              void* d_out, int out_size) {
    const float* x  = (const float*)d_in[0];
    const float* gs = (const float*)d_in[1];
    const float* gb = (const float*)d_in[2];
    const float* wq = (const float*)d_in[3];
    const float* bq = (const float*)d_in[4];
    const float* wk = (const float*)d_in[5];
    const float* bk = (const float*)d_in[6];
    const float* wv = (const float*)d_in[7];
    const float* bv = (const float*)d_in[8];
    const float* wp = (const float*)d_in[9];
    const float* bp = (const float*)d_in[10];
    float* out = (float*)d_out;

    cudaFuncSetAttribute(gemm_kernel<MODE_COLB, 8>,   cudaFuncAttributeMaxDynamicSharedMemorySize, GSMEM);
    cudaFuncSetAttribute(gemm_kernel<MODE_ROWB, 8>,   cudaFuncAttributeMaxDynamicSharedMemorySize, GSMEM);
    cudaFuncSetAttribute(gemm_kernel<MODE_SCALE, 8>,  cudaFuncAttributeMaxDynamicSharedMemorySize, GSMEM);
    cudaFuncSetAttribute(gemm_kernel<MODE_NONE, 32>,  cudaFuncAttributeMaxDynamicSharedMemorySize, GSMEM);
    cudaFuncSetAttribute(gemm_kernel<MODE_OUT, 8>,    cudaFuncAttributeMaxDynamicSharedMemorySize, GSMEM);

    __half* hTh  = nullptr; cudaGetSymbolAddress((void**)&hTh,  g_hTh);
    __half* qTh  = nullptr; cudaGetSymbolAddress((void**)&qTh,  g_qTh);
    __half* kTh  = nullptr; cudaGetSymbolAddress((void**)&kTh,  g_kTh);
    __half* vh   = nullptr; cudaGetSymbolAddress((void**)&vh,   g_vh);
    float*  p    = nullptr; cudaGetSymbolAddress((void**)&p,    g_p);
    __half* ph   = nullptr; cudaGetSymbolAddress((void**)&ph,   g_ph);
    __half* h2Th = nullptr; cudaGetSymbolAddress((void**)&h2Th, g_h2Th);
    __half* wh   = nullptr; cudaGetSymbolAddress((void**)&wh,   g_wh);
    __half* wqh = wh;
    __half* wkh = wh + (size_t)C_ * C_;
    __half* wvh = wh + 2 * (size_t)C_ * C_;
    __half* wph = wh + 3 * (size_t)C_ * C_;

    cvt_w_kernel<<<dim3(C_ * C_ / 1024, 4), 256>>>(wq, wk, wv, wp);
    groupnorm_kernel<<<B_ * GROUPS_, 256>>>(x, gs, gb);

    // merged qT+kT: z<8 -> (wq,bq,qT); z>=8 -> (wk,bk,kT).  M=2048 N=512 K=512
    gemm_kernel<MODE_COLB, 8><<<dim3(4, 16, 2 * B_), 256, GSMEM>>>(
        hTh, wqh, qTh, bq, nullptr, wkh, bk, kTh, C_, C_, C_, NC_, 0, NC_, 0);
    // v[o][n] = sum_c wv[o][c] hT[n][c] + bv[o]       M=512 N=2048 K=512
    gemm_kernel<MODE_ROWB, 8><<<dim3(16, 4, B_), 256, GSMEM>>>(
        wvh, hTh, vh, bv, nullptr, nullptr, nullptr, nullptr, C_, C_, N_, 0, NC_, NC_, 0);
    // P[i][j] = scale * sum_c qT[i][c] kT[j][c]       M=2048 N=2048 K=512 -> fp32
    gemm_kernel<MODE_SCALE, 8><<<dim3(16, 16, B_), 256, GSMEM>>>(
        qTh, kTh, p, nullptr, nullptr, nullptr, nullptr, nullptr, C_, C_, N_, NC_, NC_, NN_, 0);

    softmax_kernel<<<B_ * N_, 256>>>();

    // h2T[i][c] = sum_j P[i][j] v[c][j]               M=2048 N=512 K=2048
    gemm_kernel<MODE_NONE, 32><<<dim3(4, 16, B_), 256, GSMEM>>>(
        ph, vh, h2Th, nullptr, nullptr, nullptr, nullptr, nullptr, N_, N_, C_, NN_, NC_, NC_, 0);
    // out[o][n] = x + bp[o] + sum_c wp[o][c] h2T[n][c]  M=512 N=2048 K=512
    gemm_kernel<MODE_OUT, 8><<<dim3(16, 4, B_), 256, GSMEM>>>(
        wph, h2Th, out, bp, x, nullptr, nullptr, nullptr, C_, C_, N_, 0, NC_, NC_, NC_);
}

// round 11
// speedup vs baseline: 2.2318x; 1.0824x over previous
#include <cuda_runtime.h>
#include <cuda_fp16.h>
#include <cstdint>
#include <math.h>

#define B_   8
#define C_   512
#define N_   2048
#define GROUPS_ 32
#define CPG  16
#define EPSF 1e-6f

#define NC_ ((size_t)N_ * C_)      // 1048576
#define NN_ ((size_t)N_ * N_)      // 4194304

// ---------------- scratch ----------------
__device__ __half g_hTh [B_ * N_ * C_];          // groupnorm out, [b][n][c] half
__device__ __half g_qTh [B_ * N_ * C_];          // [b][n][c]
__device__ __half g_kTh [B_ * N_ * C_];          // [b][n][c]
__device__ __half g_vh  [B_ * C_ * N_];          // [b][c][n]
__device__ __half g_ph  [(size_t)B_ * N_ * N_];  // logits -> probs, half, in-place
__device__ __half g_h2Th[B_ * N_ * C_];          // [b][i][c]
__device__ __half g_wh  [4 * C_ * C_];           // wq,wk,wv,wp as half

// ---------------- helpers ----------------
__device__ __forceinline__ uint32_t smem_u32(const void* p) {
    uint32_t a;
    asm("{ .reg .u64 t; cvta.to.shared.u64 t, %1; cvt.u32.u64 %0, t; }" : "=r"(a) : "l"(p));
    return a;
}
__device__ __forceinline__ void cp_async16(uint32_t dst, const void* src) {
    asm volatile("cp.async.cg.shared.global [%0], [%1], 16;" :: "r"(dst), "l"(src));
}
#define CP_COMMIT() asm volatile("cp.async.commit_group;" ::: "memory")
#define CP_WAIT0()  asm volatile("cp.async.wait_group 0;" ::: "memory")

__device__ __forceinline__ void mma_f16(float* c, const uint32_t* a, const uint32_t* b) {
    asm volatile("mma.sync.aligned.m16n8k16.row.col.f32.f16.f16.f32 "
                 "{%0,%1,%2,%3}, {%4,%5,%6,%7}, {%8,%9}, {%0,%1,%2,%3};"
                 : "+f"(c[0]), "+f"(c[1]), "+f"(c[2]), "+f"(c[3])
                 : "r"(a[0]), "r"(a[1]), "r"(a[2]), "r"(a[3]), "r"(b[0]), "r"(b[1]));
}
__device__ __forceinline__ void ldm_x4(uint32_t& r0, uint32_t& r1, uint32_t& r2, uint32_t& r3,
                                       uint32_t addr) {
    asm volatile("ldmatrix.sync.aligned.m8n8.x4.shared.b16 {%0,%1,%2,%3}, [%4];"
                 : "=r"(r0), "=r"(r1), "=r"(r2), "=r"(r3) : "r"(addr));
}

// ---------------- weight fp32 -> fp16 ----------------
__global__ __launch_bounds__(256) void cvt_w_kernel(const float* __restrict__ wq,
                                                    const float* __restrict__ wk,
                                                    const float* __restrict__ wv,
                                                    const float* __restrict__ wp) {
    const float* src = (blockIdx.y == 0) ? wq : (blockIdx.y == 1) ? wk
                       : (blockIdx.y == 2) ? wv : wp;
    __half* dst = g_wh + (size_t)blockIdx.y * C_ * C_;
    int i = (blockIdx.x * 256 + threadIdx.x) * 4;
    float4 v = *(const float4*)(src + i);
    __half2 h0 = __floats2half2_rn(v.x, v.y);
    __half2 h1 = __floats2half2_rn(v.z, v.w);
    *(uint2*)(dst + i) = make_uint2(*(uint32_t*)&h0, *(uint32_t*)&h1);
}

// ---------------- GroupNorm (writes transposed half hT[b][n][c]) ----------------
__global__ __launch_bounds__(256) void groupnorm_kernel(const float* __restrict__ x,
                                                        const float* __restrict__ scale,
                                                        const float* __restrict__ bias) {
    int bg = blockIdx.x;
    int b = bg / GROUPS_, g = bg % GROUPS_;
    const float* xp  = x + ((size_t)b * C_ + (size_t)g * CPG) * N_;
    __half*      hpT = g_hTh + (size_t)b * NC_;
    int tid = threadIdx.x;
    const int total = CPG * N_;  // 32768

    float s = 0.f, ss = 0.f;
    for (int i = tid; i < total; i += 256) {
        float v = xp[i];
        s += v; ss += v * v;
    }
    __shared__ float rs[256], rq[256];
    rs[tid] = s; rq[tid] = ss;
    __syncthreads();
    for (int off = 128; off > 0; off >>= 1) {
        if (tid < off) { rs[tid] += rs[tid + off]; rq[tid] += rq[tid + off]; }
        __syncthreads();
    }
    float mean = rs[0] / (float)total;
    float var  = rq[0] / (float)total - mean * mean;
    float rinv = rsqrtf(var + EPSF);

    __shared__ float tile[128][17];
    for (int n0 = 0; n0 < N_; n0 += 128) {
        __syncthreads();
        int nl = tid & 127;
        int ch = tid >> 7;
        #pragma unroll
        for (int cp = 0; cp < 8; cp++) {
            int c = cp * 2 + ch;
            int cabs = g * CPG + c;
            tile[nl][c] = (xp[(size_t)c * N_ + n0 + nl] - mean) * rinv * scale[cabs] + bias[cabs];
        }
        __syncthreads();
        int row = tid >> 1;
        int half = (tid & 1) * 8;
        __half* dst = hpT + (size_t)(n0 + row) * C_ + g * CPG + half;
        __half2 h0 = __floats2half2_rn(tile[row][half + 0], tile[row][half + 1]);
        __half2 h1 = __floats2half2_rn(tile[row][half + 2], tile[row][half + 3]);
        __half2 h2 = __floats2half2_rn(tile[row][half + 4], tile[row][half + 5]);
        __half2 h3 = __floats2half2_rn(tile[row][half + 6], tile[row][half + 7]);
        *(uint4*)dst = make_uint4(*(uint32_t*)&h0, *(uint32_t*)&h1,
                                  *(uint32_t*)&h2, *(uint32_t*)&h3);
    }
}

// ---------------- fp16 mma.sync GEMM (ldmatrix fragments) ----------------
// D[m][n] = sum_k A[m][k] * B[n][k], both K-major half.
#define MODE_COLB  0   // + bias[col], D half      (qT / kT dual)
#define MODE_ROWB  1   // + bias[row], D half      (v)
#define MODE_SCALE 2   // * scale,     D half      (QK logits)
#define MODE_NONE  3   //              D half      (PV)
#define MODE_OUT   4   // + bias[row] + resid, D float

#define BKH    64            // K-chunk in halves
#define PADH   72            // row pitch halves; banks (4r+t)%32 distinct per 8x8 matrix
#define STAGEH (128 * PADH)
#define GSMEM  (3 * 2 * STAGEH * 2)   // 110592 bytes

template <int MODE, int NCK>
__global__ __launch_bounds__(256, 2)
void gemm_kernel(const __half* __restrict__ A, const __half* __restrict__ Bm,
                 void* __restrict__ Dv,
                 const float* __restrict__ bias, const float* __restrict__ resid,
                 const __half* __restrict__ Bm2, const float* __restrict__ bias2,
                 void* __restrict__ Dv2,
                 int lda, int ldb, int ldd,
                 size_t a_bs, size_t b_bs, size_t d_bs, size_t r_bs) {
    extern __shared__ __half smem[];

    int tid = threadIdx.x, lane = tid & 31, wid = tid >> 5;
    int warp_m = wid & 3;
    int warp_n = wid >> 2;

    int b = blockIdx.z;
    const __half* Bsel = Bm;
    const float*  bsel = bias;
    void*         Dsel = Dv;
    if (MODE == MODE_COLB) {
        int half = gridDim.z >> 1;
        if ((int)blockIdx.z >= half) {
            b = blockIdx.z - half;
            Bsel = Bm2; bsel = bias2; Dsel = Dv2;
        }
    }

    int m0 = blockIdx.y * 128, n0 = blockIdx.x * 128;
    const __half* Ab = A    + (size_t)b * a_bs;
    const __half* Bb = Bsel + (size_t)b * b_bs;

    uint32_t sbase = smem_u32(smem);

    auto load_stage = [&](int stage, int k0) {
        uint32_t sa = sbase + (uint32_t)stage * (2u * STAGEH * 2u);
        uint32_t sb = sa + STAGEH * 2u;
        #pragma unroll
        for (int t = 0; t < 4; t++) {
            int idx = t * 256 + tid;
            int r = idx >> 3, c = idx & 7;
            uint32_t off = (uint32_t)(r * PADH + c * 8) * 2u;
            cp_async16(sa + off, Ab + (size_t)(m0 + r) * lda + k0 + c * 8);
            cp_async16(sb + off, Bb + (size_t)(n0 + r) * ldb + k0 + c * 8);
        }
    };

    // ldmatrix lane address offsets (in halves, before *2 bytes)
    int l7  = lane & 7;
    int l8  = (lane >> 3) & 1;
    int l16 = lane >> 4;
    // A x4 tiles: (m0k0),(m8k0),(m0k8),(m8k8):  row = base + l7 + l8*8, col = l16*8
    int aoff = (warp_m * 32 + l7 + l8 * 8) * PADH + l16 * 8;
    // B x4 tiles: (n0k0),(n0k8),(n8k0),(n8k8):  row = base + l7 + l16*8, col = l8*8
    int boff = (warp_n * 64 + l7 + l16 * 8) * PADH + l8 * 8;

    auto ldfragA = [&](uint32_t sa, int kbase, uint32_t fa[2][4]) {
        #pragma unroll
        for (int mt = 0; mt < 2; mt++) {
            uint32_t addr = sa + (uint32_t)(aoff + mt * 16 * PADH + kbase) * 2u;
            ldm_x4(fa[mt][0], fa[mt][1], fa[mt][2], fa[mt][3], addr);
        }
    };
    auto ldfragB = [&](uint32_t sb, int kbase, uint32_t fb[8][2]) {
        #pragma unroll
        for (int pp = 0; pp < 4; pp++) {
            uint32_t addr = sb + (uint32_t)(boff + pp * 16 * PADH + kbase) * 2u;
            ldm_x4(fb[2 * pp][0], fb[2 * pp][1], fb[2 * pp + 1][0], fb[2 * pp + 1][1], addr);
        }
    };

    float acc[2][8][4];
    #pragma unroll
    for (int i = 0; i < 2; i++)
        #pragma unroll
        for (int j = 0; j < 8; j++)
            #pragma unroll
            for (int t = 0; t < 4; t++) acc[i][j][t] = 0.f;

    uint32_t fA[2][2][4];
    uint32_t fB[2][8][2];

    load_stage(0, 0);
    CP_COMMIT();
    CP_WAIT0();
    __syncthreads();
    load_stage(1, BKH);
    CP_COMMIT();
    {
        uint32_t sa0 = sbase;
        uint32_t sb0 = sbase + STAGEH * 2u;
        ldfragA(sa0, 0, fA[0]);
        ldfragB(sb0, 0, fB[0]);
    }

    int stage = 0;
    #pragma unroll 1
    for (int ck = 0; ck < NCK; ck++) {
        CP_WAIT0();
        __syncthreads();

        int lst = stage + 2; if (lst >= 3) lst -= 3;
        if (ck + 2 < NCK) load_stage(lst, (ck + 2) * BKH);
        CP_COMMIT();

        uint32_t sa = sbase + (uint32_t)stage * (2u * STAGEH * 2u);
        uint32_t sb = sa + STAGEH * 2u;
        int nst = stage + 1; if (nst >= 3) nst -= 3;
        uint32_t xsa = sbase + (uint32_t)nst * (2u * STAGEH * 2u);
        uint32_t xsb = xsa + STAGEH * 2u;

        #pragma unroll
        for (int kk = 0; kk < 4; kk++) {
            int cur = kk & 1, nxt = cur ^ 1;
            if (kk < 3) {
                ldfragA(sa, (kk + 1) * 16, fA[nxt]);
                ldfragB(sb, (kk + 1) * 16, fB[nxt]);
            } else {
                ldfragA(xsa, 0, fA[nxt]);
                ldfragB(xsb, 0, fB[nxt]);
            }
            #pragma unroll
            for (int mt = 0; mt < 2; mt++)
                #pragma unroll
                for (int nt = 0; nt < 8; nt++)
                    mma_f16(acc[mt][nt], fA[cur][mt], fB[cur][nt]);
        }
        stage = nst;
    }

    // epilogue
    constexpr bool HALF_OUT = (MODE != MODE_OUT);
    int rbase = m0 + warp_m * 32 + (lane >> 2);
    int cbase = n0 + warp_n * 64 + (lane & 3) * 2;
    #pragma unroll
    for (int mt = 0; mt < 2; mt++) {
        int r0 = rbase + mt * 16;
        int r1 = r0 + 8;
        float rb0 = 0.f, rb1 = 0.f;
        if (MODE == MODE_ROWB || MODE == MODE_OUT) { rb0 = bsel[r0]; rb1 = bsel[r1]; }
        #pragma unroll
        for (int nt = 0; nt < 8; nt++) {
            int cc = cbase + nt * 8;
            float e0 = acc[mt][nt][0], e1 = acc[mt][nt][1];
            float e2 = acc[mt][nt][2], e3 = acc[mt][nt][3];
            if (MODE == MODE_COLB) {
                float b0 = bsel[cc], b1 = bsel[cc + 1];
                e0 += b0; e1 += b1; e2 += b0; e3 += b1;
            } else if (MODE == MODE_SCALE) {
                const float scl = 0.044194173824159216f;
                e0 *= scl; e1 *= scl; e2 *= scl; e3 *= scl;
            } else if (MODE == MODE_ROWB) {
                e0 += rb0; e1 += rb0; e2 += rb1; e3 += rb1;
            } else if (MODE == MODE_OUT) {
                const float* rp0 = resid + (size_t)b * r_bs + (size_t)r0 * ldd + cc;
                const float* rp1 = resid + (size_t)b * r_bs + (size_t)r1 * ldd + cc;
                e0 += rb0 + rp0[0]; e1 += rb0 + rp0[1];
                e2 += rb1 + rp1[0]; e3 += rb1 + rp1[1];
            }
            if (HALF_OUT) {
                __half* Dh = (__half*)Dsel + (size_t)b * d_bs;
                __half2 h0 = __floats2half2_rn(e0, e1);
                __half2 h1 = __floats2half2_rn(e2, e3);
                *(__half2*)(Dh + (size_t)r0 * ldd + cc) = h0;
                *(__half2*)(Dh + (size_t)r1 * ldd + cc) = h1;
            } else {
                float* Df = (float*)Dsel + (size_t)b * d_bs;
                float2 o0; o0.x = e0; o0.y = e1;
                float2 o1; o1.x = e2; o1.y = e3;
                *(float2*)(Df + (size_t)r0 * ldd + cc) = o0;
                *(float2*)(Df + (size_t)r1 * ldd + cc) = o1;
            }
        }
    }
}

// ---------------- row softmax: half logits -> half probs (in place) ----------------
__global__ __launch_bounds__(256) void softmax_kernel() {
    size_t row = blockIdx.x;
    uint2* p4 = (uint2*)(g_ph + row * N_);      // 4 halves per uint2
    int tid = threadIdx.x;

    uint2 ua = p4[tid];
    uint2 ub = p4[tid + 256];
    __half2 a0 = *(__half2*)&ua.x, a1 = *(__half2*)&ua.y;
    __half2 b0 = *(__half2*)&ub.x, b1 = *(__half2*)&ub.y;
    float2 fa0 = __half22float2(a0), fa1 = __half22float2(a1);
    float2 fb0 = __half22float2(b0), fb1 = __half22float2(b1);

    float mx = fmaxf(fmaxf(fmaxf(fa0.x, fa0.y), fmaxf(fa1.x, fa1.y)),
                     fmaxf(fmaxf(fb0.x, fb0.y), fmaxf(fb1.x, fb1.y)));

    __shared__ float red[256];
    red[tid] = mx; __syncthreads();
    for (int off = 128; off > 0; off >>= 1) {
        if (tid < off) red[tid] = fmaxf(red[tid], red[tid + off]);
        __syncthreads();
    }
    mx = red[0]; __syncthreads();

    fa0.x = __expf(fa0.x - mx); fa0.y = __expf(fa0.y - mx);
    fa1.x = __expf(fa1.x - mx); fa1.y = __expf(fa1.y - mx);
    fb0.x = __expf(fb0.x - mx); fb0.y = __expf(fb0.y - mx);
    fb1.x = __expf(fb1.x - mx); fb1.y = __expf(fb1.y - mx);
    float s = (fa0.x + fa0.y + fa1.x + fa1.y) + (fb0.x + fb0.y + fb1.x + fb1.y);

    red[tid] = s; __syncthreads();
    for (int off = 128; off > 0; off >>= 1) {
        if (tid < off) red[tid] += red[tid + off];
        __syncthreads();
    }
    float rinv = 1.f / red[0];

    __half2 oa0 = __floats2half2_rn(fa0.x * rinv, fa0.y * rinv);
    __half2 oa1 = __floats2half2_rn(fa1.x * rinv, fa1.y * rinv);
    __half2 ob0 = __floats2half2_rn(fb0.x * rinv, fb0.y * rinv);
    __half2 ob1 = __floats2half2_rn(fb1.x * rinv, fb1.y * rinv);
    p4[tid]       = make_uint2(*(uint32_t*)&oa0, *(uint32_t*)&oa1);
    p4[tid + 256] = make_uint2(*(uint32_t*)&ob0, *(uint32_t*)&ob1);
}

// ---------------- launch ----------------
extern "C" void kernel_launch(void* const* d_in, const int* in_sizes, int n_in,
                              void* d_out, int out_size) {
    const float* x  = (const float*)d_in[0];
    const float* gs = (const float*)d_in[1];
    const float* gb = (const float*)d_in[2];
    const float* wq = (const float*)d_in[3];
    const float* bq = (const float*)d_in[4];
    const float* wk = (const float*)d_in[5];
    const float* bk = (const float*)d_in[6];
    const float* wv = (const float*)d_in[7];
    const float* bv = (const float*)d_in[8];
    const float* wp = (const float*)d_in[9];
    const float* bp = (const float*)d_in[10];
    float* out = (float*)d_out;

    cudaFuncSetAttribute(gemm_kernel<MODE_COLB, 8>,   cudaFuncAttributeMaxDynamicSharedMemorySize, GSMEM);
    cudaFuncSetAttribute(gemm_kernel<MODE_ROWB, 8>,   cudaFuncAttributeMaxDynamicSharedMemorySize, GSMEM);
    cudaFuncSetAttribute(gemm_kernel<MODE_SCALE, 8>,  cudaFuncAttributeMaxDynamicSharedMemorySize, GSMEM);
    cudaFuncSetAttribute(gemm_kernel<MODE_NONE, 32>,  cudaFuncAttributeMaxDynamicSharedMemorySize, GSMEM);
    cudaFuncSetAttribute(gemm_kernel<MODE_OUT, 8>,    cudaFuncAttributeMaxDynamicSharedMemorySize, GSMEM);

    __half* hTh  = nullptr; cudaGetSymbolAddress((void**)&hTh,  g_hTh);
    __half* qTh  = nullptr; cudaGetSymbolAddress((void**)&qTh,  g_qTh);
    __half* kTh  = nullptr; cudaGetSymbolAddress((void**)&kTh,  g_kTh);
    __half* vh   = nullptr; cudaGetSymbolAddress((void**)&vh,   g_vh);
    __half* ph   = nullptr; cudaGetSymbolAddress((void**)&ph,   g_ph);
    __half* h2Th = nullptr; cudaGetSymbolAddress((void**)&h2Th, g_h2Th);
    __half* wh   = nullptr; cudaGetSymbolAddress((void**)&wh,   g_wh);
    __half* wqh = wh;
    __half* wkh = wh + (size_t)C_ * C_;
    __half* wvh = wh + 2 * (size_t)C_ * C_;
    __half* wph = wh + 3 * (size_t)C_ * C_;

    cvt_w_kernel<<<dim3(C_ * C_ / 1024, 4), 256>>>(wq, wk, wv, wp);
    groupnorm_kernel<<<B_ * GROUPS_, 256>>>(x, gs, gb);

    // merged qT+kT: z<8 -> (wq,bq,qT); z>=8 -> (wk,bk,kT).  M=2048 N=512 K=512
    gemm_kernel<MODE_COLB, 8><<<dim3(4, 16, 2 * B_), 256, GSMEM>>>(
        hTh, wqh, qTh, bq, nullptr, wkh, bk, kTh, C_, C_, C_, NC_, 0, NC_, 0);
    // v[o][n] = sum_c wv[o][c] hT[n][c] + bv[o]       M=512 N=2048 K=512
    gemm_kernel<MODE_ROWB, 8><<<dim3(16, 4, B_), 256, GSMEM>>>(
        wvh, hTh, vh, bv, nullptr, nullptr, nullptr, nullptr, C_, C_, N_, 0, NC_, NC_, 0);
    // logits[i][j] = scale * sum_c qT[i][c] kT[j][c]  M=2048 N=2048 K=512 -> half
    gemm_kernel<MODE_SCALE, 8><<<dim3(16, 16, B_), 256, GSMEM>>>(
        qTh, kTh, ph, nullptr, nullptr, nullptr, nullptr, nullptr, C_, C_, N_, NC_, NC_, NN_, 0);

    softmax_kernel<<<B_ * N_, 256>>>();

    // h2T[i][c] = sum_j P[i][j] v[c][j]               M=2048 N=512 K=2048
    gemm_kernel<MODE_NONE, 32><<<dim3(4, 16, B_), 256, GSMEM>>>(
        ph, vh, h2Th, nullptr, nullptr, nullptr, nullptr, nullptr, N_, N_, C_, NN_, NC_, NC_, 0);
    // out[o][n] = x + bp[o] + sum_c wp[o][c] h2T[n][c]  M=512 N=2048 K=512
    gemm_kernel<MODE_OUT, 8><<<dim3(16, 4, B_), 256, GSMEM>>>(
        wph, h2Th, out, bp, x, nullptr, nullptr, nullptr, C_, C_, N_, 0, NC_, NC_, NC_);
}